// round 1
// baseline (speedup 1.0000x reference)
#include <cuda_runtime.h>
#include <math.h>

#define N_NODES 100000
#define N_EDGES 1600000
#define IN_C    128
#define HID_C   256
#define OUT_C   47
#define OUTP    48

// ---------------- scratch (static __device__, no allocs) ----------------
__device__ float g_mean1[(size_t)N_NODES * IN_C];   // mean-aggregated x  (51.2 MB)
__device__ float g_h[(size_t)N_NODES * HID_C];      // relu(conv1)       (102.4 MB)
__device__ float g_yl[(size_t)N_NODES * OUTP];      // h @ W2_l (padded) (19.2 MB)
__device__ float g_yr[(size_t)N_NODES * OUTP];      // h @ W2_r (padded) (19.2 MB)
__device__ int   g_deg[N_NODES];
__device__ int   g_off[N_NODES + 1];
__device__ int   g_cur[N_NODES];
__device__ int   g_srcs[N_EDGES];
__device__ int   g_bsum[128];
__device__ int   g_is64;

// ---------------- f32x2 packed helpers ----------------
__device__ __forceinline__ unsigned long long pack2(float v) {
    unsigned long long r; unsigned u = __float_as_uint(v);
    asm("mov.b64 %0, {%1, %1};" : "=l"(r) : "r"(u));
    return r;
}
#define FMA_F32X2(d, a, b) asm("fma.rn.f32x2 %0, %1, %2, %0;" : "+l"(d) : "l"(a), "l"(b))

__device__ __forceinline__ float2 unpack2(unsigned long long v) {
    float2 f;
    f.x = __uint_as_float((unsigned)v);
    f.y = __uint_as_float((unsigned)(v >> 32));
    return f;
}

// ---------------- edge dtype detection ----------------
// If edge_index is int64, the high 32-bit words (odd int32 indices) of positive
// small values are all zero. If int32, odd words are random src values.
__global__ void detect_kernel(const int* __restrict__ e32) {
    if (threadIdx.x == 0) {
        int nz = 0;
        for (int i = 0; i < 64; i++) nz |= e32[2 * i + 1];
        g_is64 = (nz == 0) ? 1 : 0;
    }
}

__device__ __forceinline__ int edge_src(const void* p, int e) {
    return g_is64 ? (int)((const long long*)p)[e] : ((const int*)p)[e];
}
__device__ __forceinline__ int edge_dst(const void* p, int e) {
    return g_is64 ? (int)((const long long*)p)[N_EDGES + e] : ((const int*)p)[N_EDGES + e];
}

// ---------------- CSR build ----------------
__global__ void zero_deg_kernel() {
    int i = blockIdx.x * blockDim.x + threadIdx.x;
    if (i < N_NODES) g_deg[i] = 0;
}

__global__ void hist_kernel(const void* __restrict__ ei) {
    int e = blockIdx.x * blockDim.x + threadIdx.x;
    if (e < N_EDGES) atomicAdd(&g_deg[edge_dst(ei, e)], 1);
}

#define SCAN_B 1024
__global__ void scanA_kernel() {
    __shared__ int sm[SCAN_B];
    int tid = threadIdx.x;
    int i = blockIdx.x * SCAN_B + tid;
    int v = (i < N_NODES) ? g_deg[i] : 0;
    sm[tid] = v;
    __syncthreads();
    for (int off = 1; off < SCAN_B; off <<= 1) {
        int t = (tid >= off) ? sm[tid - off] : 0;
        __syncthreads();
        sm[tid] += t;
        __syncthreads();
    }
    if (i < N_NODES) g_off[i + 1] = sm[tid];
    if (tid == SCAN_B - 1) g_bsum[blockIdx.x] = sm[tid];
}

__global__ void scanB_kernel(int nblocks) {
    if (threadIdx.x == 0) {
        int run = 0;
        for (int b = 0; b < nblocks; b++) {
            int t = g_bsum[b];
            g_bsum[b] = run;
            run += t;
        }
    }
}

__global__ void scanC_kernel() {
    int i = blockIdx.x * SCAN_B + threadIdx.x;
    if (i < N_NODES) g_off[i + 1] += g_bsum[blockIdx.x];
    if (i == 0) g_off[0] = 0;
}

__global__ void initcur_kernel() {
    int i = blockIdx.x * blockDim.x + threadIdx.x;
    if (i < N_NODES) g_cur[i] = g_off[i];
}

__global__ void scatter_kernel(const void* __restrict__ ei) {
    int e = blockIdx.x * blockDim.x + threadIdx.x;
    if (e < N_EDGES) {
        int s = edge_src(ei, e);
        int d = edge_dst(ei, e);
        int p = atomicAdd(&g_cur[d], 1);
        g_srcs[p] = s;
    }
}

// ---------------- aggregation 1: mean of x over in-neighbors ----------------
// warp per node, lane handles one float4 of the 128-dim row
__global__ void agg1_kernel(const float* __restrict__ x) {
    int w = (blockIdx.x * blockDim.x + threadIdx.x) >> 5;
    if (w >= N_NODES) return;
    int lane = threadIdx.x & 31;
    int beg = g_off[w], end = g_off[w + 1];
    const float4* xv = (const float4*)x;
    float4 acc = make_float4(0.f, 0.f, 0.f, 0.f);
    for (int e = beg; e < end; e++) {
        int s = g_srcs[e];
        float4 v = xv[(size_t)s * 32 + lane];
        acc.x += v.x; acc.y += v.y; acc.z += v.z; acc.w += v.w;
    }
    int d = end - beg;
    float inv = 1.f / (float)max(d, 1);
    acc.x *= inv; acc.y *= inv; acc.z *= inv; acc.w *= inv;
    ((float4*)g_mean1)[(size_t)w * 32 + lane] = acc;
}

// ---------------- GEMM1: h = relu([mean|x] @ [W1l;W1r] + b1) ----------------
// BM=128, BN=128, BK=16, 256 threads, TM=8, TN=8 (4 packed f32x2 cols)
__global__ __launch_bounds__(256) void gemm1_kernel(
    const float* __restrict__ x, const float* __restrict__ W1l,
    const float* __restrict__ b1, const float* __restrict__ W1r)
{
    __shared__ __align__(16) float As[16 * 132];
    __shared__ __align__(16) float Bs[16 * 128];
    int tid = threadIdx.x;
    int tx = tid & 15, ty = tid >> 4;
    int rowBase = blockIdx.x * 128;
    int colBase = blockIdx.y * 128;

    unsigned long long acc[8][4];
#pragma unroll
    for (int i = 0; i < 8; i++)
#pragma unroll
        for (int p = 0; p < 4; p++) acc[i][p] = 0ull;

    for (int k0 = 0; k0 < 256; k0 += 16) {
        // A tile: 128x16, element = (k<128)? mean1[row][k] : x[row][k-128]
#pragma unroll
        for (int hh = 0; hh < 2; hh++) {
            int u = tid + hh * 256;
            int rl = u >> 2, k4 = (u & 3) * 4;
            int row = rowBase + rl;
            int k = k0 + k4;
            float4 v = make_float4(0.f, 0.f, 0.f, 0.f);
            if (row < N_NODES) {
                const float* src = (k < 128) ? (g_mean1 + (size_t)row * 128 + k)
                                             : (x + (size_t)row * 128 + (k - 128));
                v = *(const float4*)src;
            }
            As[(k4 + 0) * 132 + rl] = v.x;
            As[(k4 + 1) * 132 + rl] = v.y;
            As[(k4 + 2) * 132 + rl] = v.z;
            As[(k4 + 3) * 132 + rl] = v.w;
        }
        // B tile: 16x128 from [W1l;W1r]
#pragma unroll
        for (int hh = 0; hh < 2; hh++) {
            int u = tid + hh * 256;
            int kk = u >> 5, n4 = (u & 31) * 4;
            int k = k0 + kk;
            const float* src = (k < 128) ? (W1l + (size_t)k * 256 + colBase + n4)
                                         : (W1r + (size_t)(k - 128) * 256 + colBase + n4);
            *(float4*)(Bs + kk * 128 + n4) = *(const float4*)src;
        }
        __syncthreads();
#pragma unroll
        for (int kk = 0; kk < 16; kk++) {
            const float4* ap = (const float4*)(As + kk * 132 + ty * 8);
            float4 a0 = ap[0], a1 = ap[1];
            const unsigned long long* bp =
                (const unsigned long long*)(Bs + kk * 128 + tx * 8);
            unsigned long long b0 = bp[0], b1p = bp[1], b2p = bp[2], b3p = bp[3];
            float av[8] = {a0.x, a0.y, a0.z, a0.w, a1.x, a1.y, a1.z, a1.w};
#pragma unroll
            for (int i = 0; i < 8; i++) {
                unsigned long long aa = pack2(av[i]);
                FMA_F32X2(acc[i][0], aa, b0);
                FMA_F32X2(acc[i][1], aa, b1p);
                FMA_F32X2(acc[i][2], aa, b2p);
                FMA_F32X2(acc[i][3], aa, b3p);
            }
        }
        __syncthreads();
    }
    // epilogue: + bias, relu
    const float2* bb = (const float2*)(b1 + colBase + tx * 8);
    float2 bv0 = bb[0], bv1 = bb[1], bv2 = bb[2], bv3 = bb[3];
#pragma unroll
    for (int i = 0; i < 8; i++) {
        int row = rowBase + ty * 8 + i;
        if (row >= N_NODES) continue;
        float2 v0 = unpack2(acc[i][0]), v1 = unpack2(acc[i][1]);
        float2 v2 = unpack2(acc[i][2]), v3 = unpack2(acc[i][3]);
        float4 o0 = make_float4(fmaxf(v0.x + bv0.x, 0.f), fmaxf(v0.y + bv0.y, 0.f),
                                fmaxf(v1.x + bv1.x, 0.f), fmaxf(v1.y + bv1.y, 0.f));
        float4 o1 = make_float4(fmaxf(v2.x + bv2.x, 0.f), fmaxf(v2.y + bv2.y, 0.f),
                                fmaxf(v3.x + bv3.x, 0.f), fmaxf(v3.y + bv3.y, 0.f));
        float* dst = g_h + (size_t)row * 256 + colBase + tx * 8;
        ((float4*)dst)[0] = o0;
        ((float4*)dst)[1] = o1;
    }
}

// ---------------- GEMM2: y_l = h@W2_l, y_r = h@W2_r (padded to 48 cols) ----------------
// BM=128, BN=96 (=48+48), BK=16, 256 threads, TM=8, TN=6 (3 packed f32x2 cols)
__global__ __launch_bounds__(256) void gemm2_kernel(
    const float* __restrict__ W2l, const float* __restrict__ W2r)
{
    __shared__ __align__(16) float As[16 * 132];
    __shared__ __align__(16) float Bs[16 * 96];
    int tid = threadIdx.x;
    int tx = tid & 15, ty = tid >> 4;
    int rowBase = blockIdx.x * 128;

    unsigned long long acc[8][3];
#pragma unroll
    for (int i = 0; i < 8; i++)
#pragma unroll
        for (int p = 0; p < 3; p++) acc[i][p] = 0ull;

    for (int k0 = 0; k0 < 256; k0 += 16) {
#pragma unroll
        for (int hh = 0; hh < 2; hh++) {
            int u = tid + hh * 256;
            int rl = u >> 2, k4 = (u & 3) * 4;
            int row = rowBase + rl;
            float4 v = make_float4(0.f, 0.f, 0.f, 0.f);
            if (row < N_NODES)
                v = *(const float4*)(g_h + (size_t)row * 256 + k0 + k4);
            As[(k4 + 0) * 132 + rl] = v.x;
            As[(k4 + 1) * 132 + rl] = v.y;
            As[(k4 + 2) * 132 + rl] = v.z;
            As[(k4 + 3) * 132 + rl] = v.w;
        }
        {
            int kk = tid >> 4;          // 0..15
            int nb = (tid & 15) * 6;    // 0..90
            int k = k0 + kk;
#pragma unroll
            for (int q = 0; q < 6; q++) {
                int n = nb + q;
                float v = 0.f;
                if (n < 47) v = W2l[(size_t)k * 47 + n];
                else if (n >= 48 && n < 95) v = W2r[(size_t)k * 47 + (n - 48)];
                Bs[kk * 96 + n] = v;
            }
        }
        __syncthreads();
#pragma unroll
        for (int kk = 0; kk < 16; kk++) {
            const float4* ap = (const float4*)(As + kk * 132 + ty * 8);
            float4 a0 = ap[0], a1 = ap[1];
            const unsigned long long* bp =
                (const unsigned long long*)(Bs + kk * 96 + tx * 6);
            unsigned long long b0 = bp[0], b1p = bp[1], b2p = bp[2];
            float av[8] = {a0.x, a0.y, a0.z, a0.w, a1.x, a1.y, a1.z, a1.w};
#pragma unroll
            for (int i = 0; i < 8; i++) {
                unsigned long long aa = pack2(av[i]);
                FMA_F32X2(acc[i][0], aa, b0);
                FMA_F32X2(acc[i][1], aa, b1p);
                FMA_F32X2(acc[i][2], aa, b2p);
            }
        }
        __syncthreads();
    }
    int nb = tx * 6;  // tx<8 -> entirely in y_l half (cols<48); tx>=8 -> y_r
#pragma unroll
    for (int i = 0; i < 8; i++) {
        int row = rowBase + ty * 8 + i;
        if (row >= N_NODES) continue;
        float* dst = (tx < 8) ? (g_yl + (size_t)row * OUTP + nb)
                              : (g_yr + (size_t)row * OUTP + nb - 48);
#pragma unroll
        for (int p = 0; p < 3; p++) {
            float2 v = unpack2(acc[i][p]);
            *(float2*)(dst + 2 * p) = v;
        }
    }
}

// ---------------- fused: mean-agg of y_l + bias + y_r + log_softmax ----------------
// warp per node; lanes 0..23 hold float2 (cols 2l, 2l+1), col 47 is padding
__global__ void final_kernel(const float* __restrict__ b2, float* __restrict__ out) {
    int w = (blockIdx.x * blockDim.x + threadIdx.x) >> 5;
    if (w >= N_NODES) return;
    int lane = threadIdx.x & 31;
    int beg = g_off[w], end = g_off[w + 1];
    float inv = 1.f / (float)max(end - beg, 1);
    bool act = lane < 24;
    const float2* ylv = (const float2*)g_yl;
    float2 acc = make_float2(0.f, 0.f);
    for (int e = beg; e < end; e++) {
        int s = g_srcs[e];
        if (act) {
            float2 v = ylv[(size_t)s * 24 + lane];
            acc.x += v.x; acc.y += v.y;
        }
    }
    int c0 = lane * 2, c1 = lane * 2 + 1;
    float z0 = -1e30f, z1 = -1e30f;
    if (c0 < OUT_C) z0 = acc.x * inv + b2[c0] + g_yr[(size_t)w * OUTP + c0];
    if (c1 < OUT_C) z1 = acc.y * inv + b2[c1] + g_yr[(size_t)w * OUTP + c1];
    float m = fmaxf(z0, z1);
#pragma unroll
    for (int o = 16; o > 0; o >>= 1)
        m = fmaxf(m, __shfl_xor_sync(0xffffffffu, m, o));
    float s = 0.f;
    if (c0 < OUT_C) s += expf(z0 - m);
    if (c1 < OUT_C) s += expf(z1 - m);
#pragma unroll
    for (int o = 16; o > 0; o >>= 1)
        s += __shfl_xor_sync(0xffffffffu, s, o);
    float l = logf(s);
    if (c0 < OUT_C) out[(size_t)w * OUT_C + c0] = z0 - m - l;
    if (c1 < OUT_C) out[(size_t)w * OUT_C + c1] = z1 - m - l;
}

// ---------------- launch ----------------
extern "C" void kernel_launch(void* const* d_in, const int* in_sizes, int n_in,
                              void* d_out, int out_size) {
    const float* x   = (const float*)d_in[0];
    const void*  ei  = d_in[1];
    const float* W1l = (const float*)d_in[2];
    const float* b1  = (const float*)d_in[3];
    const float* W1r = (const float*)d_in[4];
    const float* W2l = (const float*)d_in[5];
    const float* b2  = (const float*)d_in[6];
    const float* W2r = (const float*)d_in[7];
    float* out = (float*)d_out;

    const int scan_blocks = (N_NODES + SCAN_B - 1) / SCAN_B;  // 98

    detect_kernel<<<1, 32>>>((const int*)ei);
    zero_deg_kernel<<<(N_NODES + 255) / 256, 256>>>();
    hist_kernel<<<(N_EDGES + 255) / 256, 256>>>(ei);
    scanA_kernel<<<scan_blocks, SCAN_B>>>();
    scanB_kernel<<<1, 32>>>(scan_blocks);
    scanC_kernel<<<scan_blocks, SCAN_B>>>();
    initcur_kernel<<<(N_NODES + 255) / 256, 256>>>();
    scatter_kernel<<<(N_EDGES + 255) / 256, 256>>>(ei);

    agg1_kernel<<<(N_NODES * 32 + 255) / 256, 256>>>(x);

    dim3 g1((N_NODES + 127) / 128, 2);
    gemm1_kernel<<<g1, 256>>>(x, W1l, b1, W1r);

    dim3 g2((N_NODES + 127) / 128, 1);
    gemm2_kernel<<<g2, 256>>>(W2l, W2r);

    final_kernel<<<(N_NODES * 32 + 255) / 256, 256>>>(b2, out);
}

// round 3
// speedup vs baseline: 1.3515x; 1.3515x over previous
#include <cuda_runtime.h>
#include <cuda_bf16.h>
#include <math.h>
#include <stdint.h>

#define N_NODES 100000
#define N_EDGES 1600000
#define IN_C    128
#define HID_C   256
#define OUT_C   47
#define OUTP    48

// ---------------- scratch (static __device__, no allocs) ----------------
__device__ __nv_bfloat16 g_Ah[(size_t)N_NODES * HID_C];  // [mean1|x] hi
__device__ __nv_bfloat16 g_Al[(size_t)N_NODES * HID_C];  // [mean1|x] lo
__device__ __nv_bfloat16 g_Hh[(size_t)N_NODES * HID_C];  // relu(h) hi
__device__ __nv_bfloat16 g_Hl[(size_t)N_NODES * HID_C];  // relu(h) lo
__device__ __nv_bfloat16 g_W1th[256 * 256];  // [W1l;W1r]^T hi (n-major, k contiguous)
__device__ __nv_bfloat16 g_W1tl[256 * 256];
__device__ __nv_bfloat16 g_W2th[128 * 256];  // padded [W2l|W2r]^T hi
__device__ __nv_bfloat16 g_W2tl[128 * 256];
__device__ float g_yl[(size_t)N_NODES * OUTP];
__device__ float g_yr[(size_t)N_NODES * OUTP];
__device__ int   g_deg[N_NODES];
__device__ int   g_off[N_NODES + 1];
__device__ int   g_cur[N_NODES];
__device__ int   g_srcs[N_EDGES];
__device__ int   g_bsum[128];
__device__ int   g_is64;

// ---------------- helpers ----------------
__device__ __forceinline__ uint32_t smem_u32(const void* p) {
    uint32_t a;
    asm("{ .reg .u64 t; cvta.to.shared.u64 t, %1; cvt.u32.u64 %0, t; }" : "=r"(a) : "l"(p));
    return a;
}
__device__ __forceinline__ uint32_t swz(uint32_t o) { return o ^ ((o >> 3) & 0x70); }

__device__ __forceinline__ void ldsm4(uint32_t* r, uint32_t addr) {
    asm volatile("ldmatrix.sync.aligned.m8n8.x4.shared.b16 {%0,%1,%2,%3}, [%4];"
        : "=r"(r[0]), "=r"(r[1]), "=r"(r[2]), "=r"(r[3]) : "r"(addr));
}
__device__ __forceinline__ void mma_bf16(float* c, const uint32_t* a, const uint32_t* b) {
    asm volatile("mma.sync.aligned.m16n8k16.row.col.f32.bf16.bf16.f32 "
        "{%0,%1,%2,%3}, {%4,%5,%6,%7}, {%8,%9}, {%0,%1,%2,%3};"
        : "+f"(c[0]), "+f"(c[1]), "+f"(c[2]), "+f"(c[3])
        : "r"(a[0]), "r"(a[1]), "r"(a[2]), "r"(a[3]), "r"(b[0]), "r"(b[1]));
}

__device__ __forceinline__ __nv_bfloat16 bf_hi(float v) { return __float2bfloat16(v); }
__device__ __forceinline__ __nv_bfloat16 bf_lo(float v, __nv_bfloat16 h) {
    return __float2bfloat16(v - __bfloat162float(h));
}
__device__ __forceinline__ uint32_t pack_bf2(__nv_bfloat16 a, __nv_bfloat16 b) {
    __nv_bfloat162 t; t.x = a; t.y = b;
    return *(uint32_t*)&t;
}

// ---------------- edge dtype ----------------
__device__ __forceinline__ int edge_src(const void* p, int e) {
    return g_is64 ? (int)((const long long*)p)[e] : ((const int*)p)[e];
}
__device__ __forceinline__ int edge_dst(const void* p, int e) {
    return g_is64 ? (int)((const long long*)p)[N_EDGES + e] : ((const int*)p)[N_EDGES + e];
}

// ---------------- CSR build ----------------
__global__ void zero_detect_kernel(const int* __restrict__ e32) {
    int i = blockIdx.x * blockDim.x + threadIdx.x;
    if (i < N_NODES) g_deg[i] = 0;
    if (i == 0) {
        int nz = 0;
        for (int q = 0; q < 64; q++) nz |= e32[2 * q + 1];
        g_is64 = (nz == 0) ? 1 : 0;
    }
}
__global__ void hist_kernel(const void* __restrict__ ei) {
    int e = blockIdx.x * blockDim.x + threadIdx.x;
    if (e < N_EDGES) atomicAdd(&g_deg[edge_dst(ei, e)], 1);
}
#define SCAN_B 1024
__global__ void scanA_kernel() {
    __shared__ int sm[SCAN_B];
    int tid = threadIdx.x;
    int i = blockIdx.x * SCAN_B + tid;
    int v = (i < N_NODES) ? g_deg[i] : 0;
    sm[tid] = v;
    __syncthreads();
    for (int off = 1; off < SCAN_B; off <<= 1) {
        int t = (tid >= off) ? sm[tid - off] : 0;
        __syncthreads();
        sm[tid] += t;
        __syncthreads();
    }
    if (i < N_NODES) g_off[i + 1] = sm[tid];
    if (tid == SCAN_B - 1) g_bsum[blockIdx.x] = sm[tid];
}
__global__ void scanB_kernel(int nblocks) {
    if (threadIdx.x == 0) {
        int run = 0;
        for (int b = 0; b < nblocks; b++) { int t = g_bsum[b]; g_bsum[b] = run; run += t; }
    }
}
__global__ void scanC_kernel() {
    int i = blockIdx.x * SCAN_B + threadIdx.x;
    if (i < N_NODES) {
        int v = g_off[i + 1] + g_bsum[blockIdx.x];
        g_off[i + 1] = v;
        g_cur[i] = v - g_deg[i];   // == final off[i]; initcur fused
    }
    if (i == 0) g_off[0] = 0;
}
__global__ void scatter_kernel(const void* __restrict__ ei) {
    int e = blockIdx.x * blockDim.x + threadIdx.x;
    if (e < N_EDGES) {
        int s = edge_src(ei, e);
        int d = edge_dst(ei, e);
        int p = atomicAdd(&g_cur[d], 1);
        g_srcs[p] = s;
    }
}

// ---------------- weights: transpose + split (fused) ----------------
__global__ void convw_kernel(const float* __restrict__ W1l, const float* __restrict__ W1r,
                             const float* __restrict__ W2l, const float* __restrict__ W2r) {
    int idx = blockIdx.x * blockDim.x + threadIdx.x;
    if (idx < 256 * 256) {
        int n = idx >> 8, k = idx & 255;
        float v = (k < 128) ? W1l[(size_t)k * 256 + n] : W1r[(size_t)(k - 128) * 256 + n];
        __nv_bfloat16 h = bf_hi(v);
        g_W1th[idx] = h; g_W1tl[idx] = bf_lo(v, h);
    } else if (idx < 256 * 256 + 128 * 256) {
        int j = idx - 256 * 256;
        int n = j >> 8, k = j & 255;
        float v = 0.f;
        if (n < 47) v = W2l[(size_t)k * 47 + n];
        else if (n >= 48 && n < 95) v = W2r[(size_t)k * 47 + (n - 48)];
        __nv_bfloat16 h = bf_hi(v);
        g_W2th[j] = h; g_W2tl[j] = bf_lo(v, h);
    }
}

// ---------------- agg1 (+ fused xconv): A = [mean(x_nbr) | x] -> bf16 hi/lo ----------------
__global__ void agg1_kernel(const float* __restrict__ x) {
    int w = (blockIdx.x * blockDim.x + threadIdx.x) >> 5;
    if (w >= N_NODES) return;
    int lane = threadIdx.x & 31;
    int beg = g_off[w], end = g_off[w + 1];
    const float4* xv = (const float4*)x;
    float4 acc = make_float4(0.f, 0.f, 0.f, 0.f);
    for (int e = beg; e < end; e++) {
        int s = g_srcs[e];
        float4 v = xv[(size_t)s * 32 + lane];
        acc.x += v.x; acc.y += v.y; acc.z += v.z; acc.w += v.w;
    }
    float inv = 1.f / (float)max(end - beg, 1);
    acc.x *= inv; acc.y *= inv; acc.z *= inv; acc.w *= inv;
    {
        float vs[4] = {acc.x, acc.y, acc.z, acc.w};
        __nv_bfloat16 h0 = bf_hi(vs[0]), h1 = bf_hi(vs[1]), h2 = bf_hi(vs[2]), h3 = bf_hi(vs[3]);
        uint2 hp = make_uint2(pack_bf2(h0, h1), pack_bf2(h2, h3));
        uint2 lp = make_uint2(pack_bf2(bf_lo(vs[0], h0), bf_lo(vs[1], h1)),
                              pack_bf2(bf_lo(vs[2], h2), bf_lo(vs[3], h3)));
        *(uint2*)(g_Ah + (size_t)w * 256 + lane * 4) = hp;
        *(uint2*)(g_Al + (size_t)w * 256 + lane * 4) = lp;
    }
    {
        float4 v = xv[(size_t)w * 32 + lane];
        float vs[4] = {v.x, v.y, v.z, v.w};
        __nv_bfloat16 h0 = bf_hi(vs[0]), h1 = bf_hi(vs[1]), h2 = bf_hi(vs[2]), h3 = bf_hi(vs[3]);
        uint2 hp = make_uint2(pack_bf2(h0, h1), pack_bf2(h2, h3));
        uint2 lp = make_uint2(pack_bf2(bf_lo(vs[0], h0), bf_lo(vs[1], h1)),
                              pack_bf2(bf_lo(vs[2], h2), bf_lo(vs[3], h3)));
        *(uint2*)(g_Ah + (size_t)w * 256 + 128 + lane * 4) = hp;
        *(uint2*)(g_Al + (size_t)w * 256 + 128 + lane * 4) = lp;
    }
}

// ---------------- GEMM1 (HMMA): h = relu(A @ W1^T + b1), 3-term bf16 split ----------------
// BM=128, BN=128 (grid.y=2), BK=64 x 4 chunks; 8 warps (4m x 2n), warp tile 32x64
__global__ __launch_bounds__(256) void gemm1_mma(const float* __restrict__ b1) {
    extern __shared__ __align__(1024) char smm[];
    const int AH = 0, AL = 16384, WH = 32768, WL = 49152;
    uint32_t sb = smem_u32(smm);
    int tid = threadIdx.x, l = tid & 31, wid = tid >> 5;
    int wm = wid & 3, wn = wid >> 2;
    int rowBase = blockIdx.x * 128, colBase = blockIdx.y * 128;

    float acc[2][8][4];
#pragma unroll
    for (int i = 0; i < 2; i++)
#pragma unroll
        for (int j = 0; j < 8; j++)
#pragma unroll
            for (int q = 0; q < 4; q++) acc[i][j][q] = 0.f;

    int a_r0 = wm * 32 + (l & 7) + (l & 8);
    int a_kl = (l >> 4) * 8;
    int b_r0 = wn * 64 + (l & 7) + ((l >> 4) & 1) * 8;
    int b_kl = ((l >> 3) & 1) * 8;

    for (int c = 0; c < 4; c++) {
#pragma unroll
        for (int hh = 0; hh < 4; hh++) {
            int i = tid + hh * 256;
            int r = i >> 3, s = i & 7;
            uint32_t so = swz(r * 128 + s * 16);
            int row = rowBase + r;
            int4 va = make_int4(0, 0, 0, 0), vb = va;
            if (row < N_NODES) {
                size_t off = (size_t)row * 512 + c * 128 + s * 16;
                va = *(const int4*)((const char*)g_Ah + off);
                vb = *(const int4*)((const char*)g_Al + off);
            }
            *(int4*)(smm + AH + so) = va;
            *(int4*)(smm + AL + so) = vb;
            size_t woff = (size_t)(colBase + r) * 512 + c * 128 + s * 16;
            *(int4*)(smm + WH + so) = *(const int4*)((const char*)g_W1th + woff);
            *(int4*)(smm + WL + so) = *(const int4*)((const char*)g_W1tl + woff);
        }
        __syncthreads();
#pragma unroll
        for (int ks = 0; ks < 4; ks++) {
            uint32_t ah[2][4], al[2][4];
#pragma unroll
            for (int mf = 0; mf < 2; mf++) {
                uint32_t off = swz((a_r0 + mf * 16) * 128 + (ks * 16 + a_kl) * 2);
                ldsm4(ah[mf], sb + AH + off);
                ldsm4(al[mf], sb + AL + off);
            }
#pragma unroll
            for (int nf2 = 0; nf2 < 4; nf2++) {
                uint32_t off = swz((b_r0 + nf2 * 16) * 128 + (ks * 16 + b_kl) * 2);
                uint32_t bh[4], bl[4];
                ldsm4(bh, sb + WH + off);
                ldsm4(bl, sb + WL + off);
#pragma unroll
                for (int half = 0; half < 2; half++) {
                    int nf = nf2 * 2 + half;
                    uint32_t bhp[2] = {bh[half * 2], bh[half * 2 + 1]};
                    uint32_t blp[2] = {bl[half * 2], bl[half * 2 + 1]};
#pragma unroll
                    for (int mf = 0; mf < 2; mf++) {
                        mma_bf16(acc[mf][nf], ah[mf], bhp);
                        mma_bf16(acc[mf][nf], ah[mf], blp);
                        mma_bf16(acc[mf][nf], al[mf], bhp);
                    }
                }
            }
        }
        __syncthreads();
    }
    // epilogue: +bias, relu, bf16 hi/lo split store
    int er0 = rowBase + wm * 32 + (l >> 2);
    int ec0 = colBase + wn * 64 + (l & 3) * 2;
#pragma unroll
    for (int nf = 0; nf < 8; nf++) {
        int col = ec0 + nf * 8;
        float bx = __ldg(b1 + col), by = __ldg(b1 + col + 1);
#pragma unroll
        for (int mf = 0; mf < 2; mf++) {
#pragma unroll
            for (int half = 0; half < 2; half++) {
                int row = er0 + mf * 16 + half * 8;
                if (row < N_NODES) {
                    float v0 = fmaxf(acc[mf][nf][half * 2 + 0] + bx, 0.f);
                    float v1 = fmaxf(acc[mf][nf][half * 2 + 1] + by, 0.f);
                    __nv_bfloat16 h0 = bf_hi(v0), h1 = bf_hi(v1);
                    *(uint32_t*)(g_Hh + (size_t)row * 256 + col) = pack_bf2(h0, h1);
                    *(uint32_t*)(g_Hl + (size_t)row * 256 + col) =
                        pack_bf2(bf_lo(v0, h0), bf_lo(v1, h1));
                }
            }
        }
    }
}

// ---------------- GEMM2 (HMMA): [yl|yr] = H @ W2^T (N padded to 128) ----------------
__global__ __launch_bounds__(256) void gemm2_mma() {
    extern __shared__ __align__(1024) char smm[];
    const int AH = 0, AL = 16384, WH = 32768, WL = 49152;
    uint32_t sb = smem_u32(smm);
    int tid = threadIdx.x, l = tid & 31, wid = tid >> 5;
    int wm = wid & 3, wn = wid >> 2;
    int rowBase = blockIdx.x * 128;

    float acc[2][8][4];
#pragma unroll
    for (int i = 0; i < 2; i++)
#pragma unroll
        for (int j = 0; j < 8; j++)
#pragma unroll
            for (int q = 0; q < 4; q++) acc[i][j][q] = 0.f;

    int a_r0 = wm * 32 + (l & 7) + (l & 8);
    int a_kl = (l >> 4) * 8;
    int b_r0 = wn * 64 + (l & 7) + ((l >> 4) & 1) * 8;
    int b_kl = ((l >> 3) & 1) * 8;

    for (int c = 0; c < 4; c++) {
#pragma unroll
        for (int hh = 0; hh < 4; hh++) {
            int i = tid + hh * 256;
            int r = i >> 3, s = i & 7;
            uint32_t so = swz(r * 128 + s * 16);
            int row = rowBase + r;
            int4 va = make_int4(0, 0, 0, 0), vb = va;
            if (row < N_NODES) {
                size_t off = (size_t)row * 512 + c * 128 + s * 16;
                va = *(const int4*)((const char*)g_Hh + off);
                vb = *(const int4*)((const char*)g_Hl + off);
            }
            *(int4*)(smm + AH + so) = va;
            *(int4*)(smm + AL + so) = vb;
            size_t woff = (size_t)r * 512 + c * 128 + s * 16;
            *(int4*)(smm + WH + so) = *(const int4*)((const char*)g_W2th + woff);
            *(int4*)(smm + WL + so) = *(const int4*)((const char*)g_W2tl + woff);
        }
        __syncthreads();
#pragma unroll
        for (int ks = 0; ks < 4; ks++) {
            uint32_t ah[2][4], al[2][4];
#pragma unroll
            for (int mf = 0; mf < 2; mf++) {
                uint32_t off = swz((a_r0 + mf * 16) * 128 + (ks * 16 + a_kl) * 2);
                ldsm4(ah[mf], sb + AH + off);
                ldsm4(al[mf], sb + AL + off);
            }
#pragma unroll
            for (int nf2 = 0; nf2 < 4; nf2++) {
                uint32_t off = swz((b_r0 + nf2 * 16) * 128 + (ks * 16 + b_kl) * 2);
                uint32_t bh[4], bl[4];
                ldsm4(bh, sb + WH + off);
                ldsm4(bl, sb + WL + off);
#pragma unroll
                for (int half = 0; half < 2; half++) {
                    int nf = nf2 * 2 + half;
                    uint32_t bhp[2] = {bh[half * 2], bh[half * 2 + 1]};
                    uint32_t blp[2] = {bl[half * 2], bl[half * 2 + 1]};
#pragma unroll
                    for (int mf = 0; mf < 2; mf++) {
                        mma_bf16(acc[mf][nf], ah[mf], bhp);
                        mma_bf16(acc[mf][nf], ah[mf], blp);
                        mma_bf16(acc[mf][nf], al[mf], bhp);
                    }
                }
            }
        }
        __syncthreads();
    }
    int er0 = rowBase + wm * 32 + (l >> 2);
    int ec0 = wn * 64 + (l & 3) * 2;
#pragma unroll
    for (int nf = 0; nf < 8; nf++) {
        int col = ec0 + nf * 8;
#pragma unroll
        for (int mf = 0; mf < 2; mf++) {
#pragma unroll
            for (int half = 0; half < 2; half++) {
                int row = er0 + mf * 16 + half * 8;
                if (row >= N_NODES) continue;
                float2 v = make_float2(acc[mf][nf][half * 2 + 0], acc[mf][nf][half * 2 + 1]);
                if (col < 48)
                    *(float2*)(g_yl + (size_t)row * OUTP + col) = v;
                else if (col < 96)
                    *(float2*)(g_yr + (size_t)row * OUTP + col - 48) = v;
            }
        }
    }
}

// ---------------- final: mean-agg of yl + b2 + yr + log_softmax ----------------
__global__ void final_kernel(const float* __restrict__ b2, float* __restrict__ out) {
    int w = (blockIdx.x * blockDim.x + threadIdx.x) >> 5;
    if (w >= N_NODES) return;
    int lane = threadIdx.x & 31;
    int beg = g_off[w], end = g_off[w + 1];
    float inv = 1.f / (float)max(end - beg, 1);
    bool act = lane < 24;
    const float2* ylv = (const float2*)g_yl;
    float2 acc = make_float2(0.f, 0.f);
    for (int e = beg; e < end; e++) {
        int s = g_srcs[e];
        if (act) {
            float2 v = ylv[(size_t)s * 24 + lane];
            acc.x += v.x; acc.y += v.y;
        }
    }
    int c0 = lane * 2, c1 = lane * 2 + 1;
    float z0 = -1e30f, z1 = -1e30f;
    if (c0 < OUT_C) z0 = acc.x * inv + b2[c0] + g_yr[(size_t)w * OUTP + c0];
    if (c1 < OUT_C) z1 = acc.y * inv + b2[c1] + g_yr[(size_t)w * OUTP + c1];
    float m = fmaxf(z0, z1);
#pragma unroll
    for (int o = 16; o > 0; o >>= 1) m = fmaxf(m, __shfl_xor_sync(0xffffffffu, m, o));
    float s = 0.f;
    if (c0 < OUT_C) s += expf(z0 - m);
    if (c1 < OUT_C) s += expf(z1 - m);
#pragma unroll
    for (int o = 16; o > 0; o >>= 1) s += __shfl_xor_sync(0xffffffffu, s, o);
    float l = logf(s);
    if (c0 < OUT_C) out[(size_t)w * OUT_C + c0] = z0 - m - l;
    if (c1 < OUT_C) out[(size_t)w * OUT_C + c1] = z1 - m - l;
}

// ---------------- launch ----------------
extern "C" void kernel_launch(void* const* d_in, const int* in_sizes, int n_in,
                              void* d_out, int out_size) {
    const float* x   = (const float*)d_in[0];
    const void*  ei  = d_in[1];
    const float* W1l = (const float*)d_in[2];
    const float* b1  = (const float*)d_in[3];
    const float* W1r = (const float*)d_in[4];
    const float* W2l = (const float*)d_in[5];
    const float* b2  = (const float*)d_in[6];
    const float* W2r = (const float*)d_in[7];
    float* out = (float*)d_out;

    const int SMEM = 65536;
    cudaFuncSetAttribute(gemm1_mma, cudaFuncAttributeMaxDynamicSharedMemorySize, SMEM);
    cudaFuncSetAttribute(gemm2_mma, cudaFuncAttributeMaxDynamicSharedMemorySize, SMEM);

    const int scan_blocks = (N_NODES + SCAN_B - 1) / SCAN_B;

    zero_detect_kernel<<<(N_NODES + 255) / 256, 256>>>((const int*)ei);
    hist_kernel<<<(N_EDGES + 255) / 256, 256>>>(ei);
    scanA_kernel<<<scan_blocks, SCAN_B>>>();
    scanB_kernel<<<1, 32>>>(scan_blocks);
    scanC_kernel<<<scan_blocks, SCAN_B>>>();
    scatter_kernel<<<(N_EDGES + 255) / 256, 256>>>(ei);

    convw_kernel<<<(256 * 256 + 128 * 256 + 255) / 256, 256>>>(W1l, W1r, W2l, W2r);
    agg1_kernel<<<(N_NODES * 32 + 255) / 256, 256>>>(x);

    const int tiles = (N_NODES + 127) / 128;  // 782
    dim3 g1(tiles, 2);
    gemm1_mma<<<g1, 256, SMEM>>>(b1);
    gemm2_mma<<<tiles, 256, SMEM>>>();

    final_kernel<<<(N_NODES * 32 + 255) / 256, 256>>>(b2, out);
}

// round 4
// speedup vs baseline: 2.0795x; 1.5387x over previous
#include <cuda_runtime.h>
#include <cuda_fp16.h>
#include <math.h>
#include <stdint.h>

#define N_NODES 100000
#define N_EDGES 1600000
#define IN_C    128
#define HID_C   256
#define OUT_C   47
#define OUTP    48

// ---------------- scratch (static __device__, no allocs) ----------------
__device__ __align__(256) __half g_A[(size_t)N_NODES * HID_C];   // [mean1|x] fp16 (51.2MB)
__device__ __align__(256) __half g_H[(size_t)N_NODES * HID_C];   // relu(h) fp16
__device__ __align__(256) __half g_W1th[256 * 256];  // [W1l;W1r]^T hi (n-major, k contig)
__device__ __align__(256) __half g_W1tl[256 * 256];  // residual
__device__ __align__(256) __half g_W2th[96 * 256];   // padded [W2l|W2r]^T hi (rows 47,95=0)
__device__ __align__(256) __half g_W2tl[96 * 256];
__device__ __align__(256) float g_yl[(size_t)N_NODES * OUTP];
__device__ __align__(256) float g_yr[(size_t)N_NODES * OUTP];
__device__ int   g_deg[N_NODES];
__device__ int   g_off[N_NODES + 1];
__device__ int   g_cur[N_NODES];
__device__ int   g_srcs[N_EDGES];
__device__ int   g_bsum[128];
__device__ int   g_is64;

// ---------------- helpers ----------------
__device__ __forceinline__ uint32_t smem_u32(const void* p) {
    uint32_t a;
    asm("{ .reg .u64 t; cvta.to.shared.u64 t, %1; cvt.u32.u64 %0, t; }" : "=r"(a) : "l"(p));
    return a;
}
__device__ __forceinline__ uint32_t swz(uint32_t o) { return o ^ ((o >> 3) & 0x70); }

__device__ __forceinline__ void ldsm4(uint32_t* r, uint32_t addr) {
    asm volatile("ldmatrix.sync.aligned.m8n8.x4.shared.b16 {%0,%1,%2,%3}, [%4];"
        : "=r"(r[0]), "=r"(r[1]), "=r"(r[2]), "=r"(r[3]) : "r"(addr));
}
__device__ __forceinline__ void mma_f16(float* c, const uint32_t* a, const uint32_t* b) {
    asm volatile("mma.sync.aligned.m16n8k16.row.col.f32.f16.f16.f32 "
        "{%0,%1,%2,%3}, {%4,%5,%6,%7}, {%8,%9}, {%0,%1,%2,%3};"
        : "+f"(c[0]), "+f"(c[1]), "+f"(c[2]), "+f"(c[3])
        : "r"(a[0]), "r"(a[1]), "r"(a[2]), "r"(a[3]), "r"(b[0]), "r"(b[1]));
}
__device__ __forceinline__ uint32_t pack_h2(__half a, __half b) {
    __half2 t; t.x = a; t.y = b;
    return *(uint32_t*)&t;
}

// ---------------- edge dtype ----------------
__device__ __forceinline__ int edge_src(const void* p, int e) {
    return g_is64 ? (int)((const long long*)p)[e] : ((const int*)p)[e];
}
__device__ __forceinline__ int edge_dst(const void* p, int e) {
    return g_is64 ? (int)((const long long*)p)[N_EDGES + e] : ((const int*)p)[N_EDGES + e];
}

// ---------------- CSR build ----------------
__global__ void zero_detect_kernel(const int* __restrict__ e32) {
    int i = blockIdx.x * blockDim.x + threadIdx.x;
    if (i < N_NODES) g_deg[i] = 0;
    if (i == 0) {
        int nz = 0;
        for (int q = 0; q < 64; q++) nz |= e32[2 * q + 1];
        g_is64 = (nz == 0) ? 1 : 0;
    }
}
__global__ void hist_kernel(const void* __restrict__ ei) {
    int e = blockIdx.x * blockDim.x + threadIdx.x;
    if (e < N_EDGES) atomicAdd(&g_deg[edge_dst(ei, e)], 1);
}
#define SCAN_B 1024
__global__ void scanA_kernel() {
    __shared__ int sm[SCAN_B];
    int tid = threadIdx.x;
    int i = blockIdx.x * SCAN_B + tid;
    int v = (i < N_NODES) ? g_deg[i] : 0;
    sm[tid] = v;
    __syncthreads();
    for (int off = 1; off < SCAN_B; off <<= 1) {
        int t = (tid >= off) ? sm[tid - off] : 0;
        __syncthreads();
        sm[tid] += t;
        __syncthreads();
    }
    if (i < N_NODES) g_off[i + 1] = sm[tid];
    if (tid == SCAN_B - 1) g_bsum[blockIdx.x] = sm[tid];
}
// scanC: adds cross-block prefix (computed in-block from g_bsum) + fuses initcur
__global__ void scanC_kernel() {
    __shared__ int wsum[4];
    __shared__ int base_s;
    int tid = threadIdx.x;
    int b = blockIdx.x;
    if (tid < 128) {
        int v = (tid < b) ? g_bsum[tid] : 0;
#pragma unroll
        for (int o = 16; o > 0; o >>= 1) v += __shfl_xor_sync(0xffffffffu, v, o);
        if ((tid & 31) == 0) wsum[tid >> 5] = v;
    }
    __syncthreads();
    if (tid == 0) base_s = wsum[0] + wsum[1] + wsum[2] + wsum[3];
    __syncthreads();
    int base = base_s;
    int i = b * SCAN_B + tid;
    if (i < N_NODES) {
        int v = g_off[i + 1] + base;
        g_off[i + 1] = v;
        g_cur[i] = v - g_deg[i];
    }
    if (i == 0) g_off[0] = 0;
}
__global__ void scatter_kernel(const void* __restrict__ ei) {
    int e = blockIdx.x * blockDim.x + threadIdx.x;
    if (e < N_EDGES) {
        int s = edge_src(ei, e);
        int d = edge_dst(ei, e);
        int p = atomicAdd(&g_cur[d], 1);
        g_srcs[p] = s;
    }
}

// ---------------- weights: transpose + fp16 hi/lo split ----------------
__global__ void convw_kernel(const float* __restrict__ W1l, const float* __restrict__ W1r,
                             const float* __restrict__ W2l, const float* __restrict__ W2r) {
    int idx = blockIdx.x * blockDim.x + threadIdx.x;
    if (idx < 256 * 256) {
        int n = idx >> 8, k = idx & 255;
        float v = (k < 128) ? W1l[(size_t)k * 256 + n] : W1r[(size_t)(k - 128) * 256 + n];
        __half h = __float2half(v);
        g_W1th[idx] = h;
        g_W1tl[idx] = __float2half(v - __half2float(h));
    } else if (idx < 256 * 256 + 96 * 256) {
        int j = idx - 256 * 256;
        int n = j >> 8, k = j & 255;
        float v = 0.f;
        if (n < 47) v = W2l[(size_t)k * 47 + n];
        else if (n >= 48 && n < 95) v = W2r[(size_t)k * 47 + (n - 48)];
        __half h = __float2half(v);
        g_W2th[j] = h;
        g_W2tl[j] = __float2half(v - __half2float(h));
    }
}

// ---------------- agg1 (+ fused xconv): A = [mean(x_nbr) | x] -> fp16 ----------------
__global__ void agg1_kernel(const float* __restrict__ x) {
    int w = (blockIdx.x * blockDim.x + threadIdx.x) >> 5;
    if (w >= N_NODES) return;
    int lane = threadIdx.x & 31;
    int beg = g_off[w], end = g_off[w + 1];
    const float4* xv = (const float4*)x;
    float4 acc = make_float4(0.f, 0.f, 0.f, 0.f);
    for (int e = beg; e < end; e++) {
        int s = g_srcs[e];
        float4 v = xv[(size_t)s * 32 + lane];
        acc.x += v.x; acc.y += v.y; acc.z += v.z; acc.w += v.w;
    }
    float inv = 1.f / (float)max(end - beg, 1);
    acc.x *= inv; acc.y *= inv; acc.z *= inv; acc.w *= inv;
    *(uint2*)(g_A + (size_t)w * 256 + lane * 4) = make_uint2(
        pack_h2(__float2half(acc.x), __float2half(acc.y)),
        pack_h2(__float2half(acc.z), __float2half(acc.w)));
    float4 v = xv[(size_t)w * 32 + lane];
    *(uint2*)(g_A + (size_t)w * 256 + 128 + lane * 4) = make_uint2(
        pack_h2(__float2half(v.x), __float2half(v.y)),
        pack_h2(__float2half(v.z), __float2half(v.w)));
}

// ---------------- GEMM1 (HMMA fp16): h = relu(A @ W1^T + b1), W 2-term ----------------
// BM=128, BN=128 (grid.y=2), BK=64 x 4 chunks; 8 warps (4m x 2n), warp tile 32x64
__global__ __launch_bounds__(256) void gemm1_mma(const float* __restrict__ b1) {
    extern __shared__ __align__(1024) char smm[];
    const int AO = 0, WH = 16384, WL = 32768;
    uint32_t sb = smem_u32(smm);
    int tid = threadIdx.x, l = tid & 31, wid = tid >> 5;
    int wm = wid & 3, wn = wid >> 2;
    int rowBase = blockIdx.x * 128, colBase = blockIdx.y * 128;

    float acc[2][8][4];
#pragma unroll
    for (int i = 0; i < 2; i++)
#pragma unroll
        for (int j = 0; j < 8; j++)
#pragma unroll
            for (int q = 0; q < 4; q++) acc[i][j][q] = 0.f;

    int a_r0 = wm * 32 + (l & 7) + (l & 8);
    int a_kl = (l >> 4) * 8;
    int b_r0 = wn * 64 + (l & 7) + ((l >> 4) & 1) * 8;
    int b_kl = ((l >> 3) & 1) * 8;

    for (int c = 0; c < 4; c++) {
        // A tile: 128x64 fp16 = 16KB -> 4 int4/thread
#pragma unroll
        for (int hh = 0; hh < 4; hh++) {
            int i = tid + hh * 256;
            int r = i >> 3, s = i & 7;
            uint32_t so = swz(r * 128 + s * 16);
            int row = rowBase + r;
            int4 va = make_int4(0, 0, 0, 0);
            if (row < N_NODES)
                va = *(const int4*)((const char*)g_A + (size_t)row * 512 + c * 128 + s * 16);
            *(int4*)(smm + AO + so) = va;
            size_t woff = (size_t)(colBase + r) * 512 + c * 128 + s * 16;
            *(int4*)(smm + WH + so) = *(const int4*)((const char*)g_W1th + woff);
            *(int4*)(smm + WL + so) = *(const int4*)((const char*)g_W1tl + woff);
        }
        __syncthreads();
#pragma unroll
        for (int ks = 0; ks < 4; ks++) {
            uint32_t ah[2][4];
#pragma unroll
            for (int mf = 0; mf < 2; mf++)
                ldsm4(ah[mf], sb + AO + swz((a_r0 + mf * 16) * 128 + (ks * 16 + a_kl) * 2));
#pragma unroll
            for (int nf2 = 0; nf2 < 4; nf2++) {
                uint32_t off = swz((b_r0 + nf2 * 16) * 128 + (ks * 16 + b_kl) * 2);
                uint32_t bh[4], bl[4];
                ldsm4(bh, sb + WH + off);
                ldsm4(bl, sb + WL + off);
#pragma unroll
                for (int half = 0; half < 2; half++) {
                    int nf = nf2 * 2 + half;
                    uint32_t bhp[2] = {bh[half * 2], bh[half * 2 + 1]};
                    uint32_t blp[2] = {bl[half * 2], bl[half * 2 + 1]};
#pragma unroll
                    for (int mf = 0; mf < 2; mf++) {
                        mma_f16(acc[mf][nf], ah[mf], bhp);
                        mma_f16(acc[mf][nf], ah[mf], blp);
                    }
                }
            }
        }
        __syncthreads();
    }
    // epilogue: +bias, relu, fp16 store
    int er0 = rowBase + wm * 32 + (l >> 2);
    int ec0 = colBase + wn * 64 + (l & 3) * 2;
#pragma unroll
    for (int nf = 0; nf < 8; nf++) {
        int col = ec0 + nf * 8;
        float bx = __ldg(b1 + col), by = __ldg(b1 + col + 1);
#pragma unroll
        for (int mf = 0; mf < 2; mf++) {
#pragma unroll
            for (int half = 0; half < 2; half++) {
                int row = er0 + mf * 16 + half * 8;
                if (row < N_NODES) {
                    float v0 = fmaxf(acc[mf][nf][half * 2 + 0] + bx, 0.f);
                    float v1 = fmaxf(acc[mf][nf][half * 2 + 1] + by, 0.f);
                    *(uint32_t*)(g_H + (size_t)row * 256 + col) =
                        pack_h2(__float2half(v0), __float2half(v1));
                }
            }
        }
    }
}

// ---------------- GEMM2 (HMMA fp16): [yl|yr] = H @ W2^T, N=96 ----------------
// 8 warps (4m x 2n), warp tile 32x48
__global__ __launch_bounds__(256) void gemm2_mma() {
    extern __shared__ __align__(1024) char smm[];
    const int AO = 0, WH = 16384, WL = 28672;  // W tiles: 96x64x2B = 12KB
    uint32_t sb = smem_u32(smm);
    int tid = threadIdx.x, l = tid & 31, wid = tid >> 5;
    int wm = wid & 3, wn = wid >> 2;
    int rowBase = blockIdx.x * 128;

    float acc[2][6][4];
#pragma unroll
    for (int i = 0; i < 2; i++)
#pragma unroll
        for (int j = 0; j < 6; j++)
#pragma unroll
            for (int q = 0; q < 4; q++) acc[i][j][q] = 0.f;

    int a_r0 = wm * 32 + (l & 7) + (l & 8);
    int a_kl = (l >> 4) * 8;
    int b_r0 = wn * 48 + (l & 7) + ((l >> 4) & 1) * 8;
    int b_kl = ((l >> 3) & 1) * 8;

    for (int c = 0; c < 4; c++) {
#pragma unroll
        for (int hh = 0; hh < 4; hh++) {
            int i = tid + hh * 256;
            int r = i >> 3, s = i & 7;
            uint32_t so = swz(r * 128 + s * 16);
            int row = rowBase + r;
            int4 va = make_int4(0, 0, 0, 0);
            if (row < N_NODES)
                va = *(const int4*)((const char*)g_H + (size_t)row * 512 + c * 128 + s * 16);
            *(int4*)(smm + AO + so) = va;
        }
        // W2 tiles: 96 rows x 64 cols x 2B = 768 int4 per dtype -> 3 iters
#pragma unroll
        for (int hh = 0; hh < 3; hh++) {
            int i = tid + hh * 256;
            int r = i >> 3, s = i & 7;
            uint32_t so = swz(r * 128 + s * 16);
            size_t woff = (size_t)r * 512 + c * 128 + s * 16;
            *(int4*)(smm + WH + so) = *(const int4*)((const char*)g_W2th + woff);
            *(int4*)(smm + WL + so) = *(const int4*)((const char*)g_W2tl + woff);
        }
        __syncthreads();
#pragma unroll
        for (int ks = 0; ks < 4; ks++) {
            uint32_t ah[2][4];
#pragma unroll
            for (int mf = 0; mf < 2; mf++)
                ldsm4(ah[mf], sb + AO + swz((a_r0 + mf * 16) * 128 + (ks * 16 + a_kl) * 2));
#pragma unroll
            for (int nf2 = 0; nf2 < 3; nf2++) {
                uint32_t off = swz((b_r0 + nf2 * 16) * 128 + (ks * 16 + b_kl) * 2);
                uint32_t bh[4], bl[4];
                ldsm4(bh, sb + WH + off);
                ldsm4(bl, sb + WL + off);
#pragma unroll
                for (int half = 0; half < 2; half++) {
                    int nf = nf2 * 2 + half;
                    uint32_t bhp[2] = {bh[half * 2], bh[half * 2 + 1]};
                    uint32_t blp[2] = {bl[half * 2], bl[half * 2 + 1]};
#pragma unroll
                    for (int mf = 0; mf < 2; mf++) {
                        mma_f16(acc[mf][nf], ah[mf], bhp);
                        mma_f16(acc[mf][nf], ah[mf], blp);
                    }
                }
            }
        }
        __syncthreads();
    }
    int er0 = rowBase + wm * 32 + (l >> 2);
    int ec0 = wn * 48 + (l & 3) * 2;
#pragma unroll
    for (int nf = 0; nf < 6; nf++) {
        int col = ec0 + nf * 8;
#pragma unroll
        for (int mf = 0; mf < 2; mf++) {
#pragma unroll
            for (int half = 0; half < 2; half++) {
                int row = er0 + mf * 16 + half * 8;
                if (row >= N_NODES) continue;
                float2 v = make_float2(acc[mf][nf][half * 2 + 0], acc[mf][nf][half * 2 + 1]);
                if (col < 48)
                    *(float2*)(g_yl + (size_t)row * OUTP + col) = v;
                else
                    *(float2*)(g_yr + (size_t)row * OUTP + col - 48) = v;
            }
        }
    }
}

// ---------------- final: mean-agg of yl + b2 + yr + log_softmax ----------------
__global__ void final_kernel(const float* __restrict__ b2, float* __restrict__ out) {
    int w = (blockIdx.x * blockDim.x + threadIdx.x) >> 5;
    if (w >= N_NODES) return;
    int lane = threadIdx.x & 31;
    int beg = g_off[w], end = g_off[w + 1];
    float inv = 1.f / (float)max(end - beg, 1);
    bool act = lane < 24;
    const float2* ylv = (const float2*)g_yl;
    float2 acc = make_float2(0.f, 0.f);
    for (int e = beg; e < end; e++) {
        int s = g_srcs[e];
        if (act) {
            float2 v = ylv[(size_t)s * 24 + lane];
            acc.x += v.x; acc.y += v.y;
        }
    }
    int c0 = lane * 2, c1 = lane * 2 + 1;
    float z0 = -1e30f, z1 = -1e30f;
    if (c0 < OUT_C) z0 = acc.x * inv + b2[c0] + g_yr[(size_t)w * OUTP + c0];
    if (c1 < OUT_C) z1 = acc.y * inv + b2[c1] + g_yr[(size_t)w * OUTP + c1];
    float m = fmaxf(z0, z1);
#pragma unroll
    for (int o = 16; o > 0; o >>= 1) m = fmaxf(m, __shfl_xor_sync(0xffffffffu, m, o));
    float s = 0.f;
    if (c0 < OUT_C) s += expf(z0 - m);
    if (c1 < OUT_C) s += expf(z1 - m);
#pragma unroll
    for (int o = 16; o > 0; o >>= 1) s += __shfl_xor_sync(0xffffffffu, s, o);
    float l = logf(s);
    if (c0 < OUT_C) out[(size_t)w * OUT_C + c0] = z0 - m - l;
    if (c1 < OUT_C) out[(size_t)w * OUT_C + c1] = z1 - m - l;
}

// ---------------- launch ----------------
extern "C" void kernel_launch(void* const* d_in, const int* in_sizes, int n_in,
                              void* d_out, int out_size) {
    const float* x   = (const float*)d_in[0];
    const void*  ei  = d_in[1];
    const float* W1l = (const float*)d_in[2];
    const float* b1  = (const float*)d_in[3];
    const float* W1r = (const float*)d_in[4];
    const float* W2l = (const float*)d_in[5];
    const float* b2  = (const float*)d_in[6];
    const float* W2r = (const float*)d_in[7];
    float* out = (float*)d_out;

    const int SMEM1 = 49152;
    const int SMEM2 = 40960;
    cudaFuncSetAttribute(gemm1_mma, cudaFuncAttributeMaxDynamicSharedMemorySize, SMEM1);
    cudaFuncSetAttribute(gemm2_mma, cudaFuncAttributeMaxDynamicSharedMemorySize, SMEM2);

    const int scan_blocks = (N_NODES + SCAN_B - 1) / SCAN_B;

    zero_detect_kernel<<<(N_NODES + 255) / 256, 256>>>((const int*)ei);
    hist_kernel<<<(N_EDGES + 255) / 256, 256>>>(ei);
    scanA_kernel<<<scan_blocks, SCAN_B>>>();
    scanC_kernel<<<scan_blocks, SCAN_B>>>();
    scatter_kernel<<<(N_EDGES + 255) / 256, 256>>>(ei);

    convw_kernel<<<(256 * 256 + 96 * 256 + 255) / 256, 256>>>(W1l, W1r, W2l, W2r);
    agg1_kernel<<<(N_NODES * 32 + 255) / 256, 256>>>(x);

    const int tiles = (N_NODES + 127) / 128;  // 782
    dim3 g1(tiles, 2);
    gemm1_mma<<<g1, 256, SMEM1>>>(b1);
    gemm2_mma<<<tiles, 256, SMEM2>>>();

    final_kernel<<<(N_NODES * 32 + 255) / 256, 256>>>(b2, out);
}

// round 5
// speedup vs baseline: 2.2094x; 1.0624x over previous
#include <cuda_runtime.h>
#include <cuda_fp16.h>
#include <math.h>
#include <stdint.h>

#define N_NODES 100000
#define N_EDGES 1600000
#define IN_C    128
#define HID_C   256
#define OUT_C   47
#define OUTP    48

// ---------------- scratch (static __device__, no allocs) ----------------
__device__ __align__(256) __half g_Xh[(size_t)N_NODES * IN_C];   // x fp16 compact (25.6MB)
__device__ __align__(256) __half g_A[(size_t)N_NODES * HID_C];   // [mean1|x] fp16 (51.2MB)
__device__ __align__(256) __half g_H[(size_t)N_NODES * HID_C];   // relu(h) fp16
__device__ __align__(256) __half g_W1t[256 * 256];  // [W1l;W1r]^T fp16 (n-major, k contig)
__device__ __align__(256) __half g_W2t[96 * 256];   // padded [W2l|W2r]^T fp16 (rows 47,95=0)
__device__ __align__(256) float g_yl[(size_t)N_NODES * OUTP];
__device__ __align__(256) float g_yr[(size_t)N_NODES * OUTP];
__device__ int   g_deg[N_NODES];
__device__ int   g_off[N_NODES + 1];
__device__ int   g_cur[N_NODES];
__device__ int   g_srcs[N_EDGES];
__device__ int   g_bsum[128];
__device__ int   g_is64;

// ---------------- helpers ----------------
__device__ __forceinline__ uint32_t smem_u32(const void* p) {
    uint32_t a;
    asm("{ .reg .u64 t; cvta.to.shared.u64 t, %1; cvt.u32.u64 %0, t; }" : "=r"(a) : "l"(p));
    return a;
}
__device__ __forceinline__ uint32_t swz(uint32_t o) { return o ^ ((o >> 3) & 0x70); }

__device__ __forceinline__ void ldsm4(uint32_t* r, uint32_t addr) {
    asm volatile("ldmatrix.sync.aligned.m8n8.x4.shared.b16 {%0,%1,%2,%3}, [%4];"
        : "=r"(r[0]), "=r"(r[1]), "=r"(r[2]), "=r"(r[3]) : "r"(addr));
}
__device__ __forceinline__ void mma_f16(float* c, const uint32_t* a, const uint32_t* b) {
    asm volatile("mma.sync.aligned.m16n8k16.row.col.f32.f16.f16.f32 "
        "{%0,%1,%2,%3}, {%4,%5,%6,%7}, {%8,%9}, {%0,%1,%2,%3};"
        : "+f"(c[0]), "+f"(c[1]), "+f"(c[2]), "+f"(c[3])
        : "r"(a[0]), "r"(a[1]), "r"(a[2]), "r"(a[3]), "r"(b[0]), "r"(b[1]));
}
__device__ __forceinline__ uint32_t pack_h2(__half a, __half b) {
    __half2 t; t.x = a; t.y = b;
    return *(uint32_t*)&t;
}

// ---------------- edge dtype ----------------
__device__ __forceinline__ int edge_src(const void* p, int e) {
    return g_is64 ? (int)((const long long*)p)[e] : ((const int*)p)[e];
}
__device__ __forceinline__ int edge_dst(const void* p, int e) {
    return g_is64 ? (int)((const long long*)p)[N_EDGES + e] : ((const int*)p)[N_EDGES + e];
}

// ---------------- fused: deg-zero + dtype detect + x->fp16 (compact + A x-half) ----------------
__global__ void prep_kernel(const float* __restrict__ x, const int* __restrict__ e32) {
    int t = blockIdx.x * blockDim.x + threadIdx.x;  // N_NODES*32 threads
    if (t < N_NODES) g_deg[t] = 0;
    if (t == 0) {
        int nz = 0;
        for (int q = 0; q < 64; q++) nz |= e32[2 * q + 1];
        g_is64 = (nz == 0) ? 1 : 0;
    }
    if (t >= N_NODES * 32) return;
    int row = t >> 5, q = t & 31;
    float4 v = ((const float4*)x)[(size_t)row * 32 + q];
    uint2 p = make_uint2(pack_h2(__float2half(v.x), __float2half(v.y)),
                         pack_h2(__float2half(v.z), __float2half(v.w)));
    *(uint2*)(g_Xh + (size_t)row * 128 + q * 4) = p;
    *(uint2*)(g_A + (size_t)row * 256 + 128 + q * 4) = p;
}

// ---------------- CSR build ----------------
__global__ void hist_kernel(const void* __restrict__ ei) {
    int e = blockIdx.x * blockDim.x + threadIdx.x;
    if (e < N_EDGES) atomicAdd(&g_deg[edge_dst(ei, e)], 1);
}
#define SCAN_B 1024
__global__ void scanA_kernel() {
    __shared__ int sm[SCAN_B];
    int tid = threadIdx.x;
    int i = blockIdx.x * SCAN_B + tid;
    int v = (i < N_NODES) ? g_deg[i] : 0;
    sm[tid] = v;
    __syncthreads();
    for (int off = 1; off < SCAN_B; off <<= 1) {
        int t = (tid >= off) ? sm[tid - off] : 0;
        __syncthreads();
        sm[tid] += t;
        __syncthreads();
    }
    if (i < N_NODES) g_off[i + 1] = sm[tid];
    if (tid == SCAN_B - 1) g_bsum[blockIdx.x] = sm[tid];
}
// scanC: adds cross-block prefix (computed in-block from g_bsum) + fuses initcur
__global__ void scanC_kernel() {
    __shared__ int wsum[4];
    __shared__ int base_s;
    int tid = threadIdx.x;
    int b = blockIdx.x;
    if (tid < 128) {
        int v = (tid < b) ? g_bsum[tid] : 0;
#pragma unroll
        for (int o = 16; o > 0; o >>= 1) v += __shfl_xor_sync(0xffffffffu, v, o);
        if ((tid & 31) == 0) wsum[tid >> 5] = v;
    }
    __syncthreads();
    if (tid == 0) base_s = wsum[0] + wsum[1] + wsum[2] + wsum[3];
    __syncthreads();
    int base = base_s;
    int i = b * SCAN_B + tid;
    if (i < N_NODES) {
        int v = g_off[i + 1] + base;
        g_off[i + 1] = v;
        g_cur[i] = v - g_deg[i];
    }
    if (i == 0) g_off[0] = 0;
}
__global__ void scatter_kernel(const void* __restrict__ ei) {
    int e = blockIdx.x * blockDim.x + threadIdx.x;
    if (e < N_EDGES) {
        int s = edge_src(ei, e);
        int d = edge_dst(ei, e);
        int p = atomicAdd(&g_cur[d], 1);
        g_srcs[p] = s;
    }
}

// ---------------- weights: transpose to fp16 ----------------
__global__ void convw_kernel(const float* __restrict__ W1l, const float* __restrict__ W1r,
                             const float* __restrict__ W2l, const float* __restrict__ W2r) {
    int idx = blockIdx.x * blockDim.x + threadIdx.x;
    if (idx < 256 * 256) {
        int n = idx >> 8, k = idx & 255;
        float v = (k < 128) ? W1l[(size_t)k * 256 + n] : W1r[(size_t)(k - 128) * 256 + n];
        g_W1t[idx] = __float2half(v);
    } else if (idx < 256 * 256 + 96 * 256) {
        int j = idx - 256 * 256;
        int n = j >> 8, k = j & 255;
        float v = 0.f;
        if (n < 47) v = W2l[(size_t)k * 47 + n];
        else if (n >= 48 && n < 95) v = W2r[(size_t)k * 47 + (n - 48)];
        g_W2t[j] = __float2half(v);
    }
}

// ---------------- agg1: mean of fp16 x over in-neighbors -> fp16 A lo half ----------------
__global__ void agg1_kernel() {
    int w = (blockIdx.x * blockDim.x + threadIdx.x) >> 5;
    if (w >= N_NODES) return;
    int lane = threadIdx.x & 31;
    int beg = g_off[w], end = g_off[w + 1];
    const uint2* xv = (const uint2*)g_Xh;
    float4 acc = make_float4(0.f, 0.f, 0.f, 0.f);
    for (int e = beg; e < end; e++) {
        int s = g_srcs[e];
        uint2 p = xv[(size_t)s * 32 + lane];
        float2 a = __half22float2(*(__half2*)&p.x);
        float2 b = __half22float2(*(__half2*)&p.y);
        acc.x += a.x; acc.y += a.y; acc.z += b.x; acc.w += b.y;
    }
    float inv = 1.f / (float)max(end - beg, 1);
    *(uint2*)(g_A + (size_t)w * 256 + lane * 4) = make_uint2(
        pack_h2(__float2half(acc.x * inv), __float2half(acc.y * inv)),
        pack_h2(__float2half(acc.z * inv), __float2half(acc.w * inv)));
}

// ---------------- GEMM1 (HMMA fp16): h = relu(A @ W1^T + b1) ----------------
// BM=128, BN=128 (grid.y=2), BK=64 x 4 chunks; 8 warps (4m x 2n), warp tile 32x64
__global__ __launch_bounds__(256) void gemm1_mma(const float* __restrict__ b1) {
    extern __shared__ __align__(1024) char smm[];
    const int AO = 0, WO = 16384;
    uint32_t sb = smem_u32(smm);
    int tid = threadIdx.x, l = tid & 31, wid = tid >> 5;
    int wm = wid & 3, wn = wid >> 2;
    int rowBase = blockIdx.x * 128, colBase = blockIdx.y * 128;

    float acc[2][8][4];
#pragma unroll
    for (int i = 0; i < 2; i++)
#pragma unroll
        for (int j = 0; j < 8; j++)
#pragma unroll
            for (int q = 0; q < 4; q++) acc[i][j][q] = 0.f;

    int a_r0 = wm * 32 + (l & 7) + (l & 8);
    int a_kl = (l >> 4) * 8;
    int b_r0 = wn * 64 + (l & 7) + ((l >> 4) & 1) * 8;
    int b_kl = ((l >> 3) & 1) * 8;

    for (int c = 0; c < 4; c++) {
#pragma unroll
        for (int hh = 0; hh < 4; hh++) {
            int i = tid + hh * 256;
            int r = i >> 3, s = i & 7;
            uint32_t so = swz(r * 128 + s * 16);
            int row = rowBase + r;
            int4 va = make_int4(0, 0, 0, 0);
            if (row < N_NODES)
                va = *(const int4*)((const char*)g_A + (size_t)row * 512 + c * 128 + s * 16);
            *(int4*)(smm + AO + so) = va;
            size_t woff = (size_t)(colBase + r) * 512 + c * 128 + s * 16;
            *(int4*)(smm + WO + so) = *(const int4*)((const char*)g_W1t + woff);
        }
        __syncthreads();
#pragma unroll
        for (int ks = 0; ks < 4; ks++) {
            uint32_t ah[2][4];
#pragma unroll
            for (int mf = 0; mf < 2; mf++)
                ldsm4(ah[mf], sb + AO + swz((a_r0 + mf * 16) * 128 + (ks * 16 + a_kl) * 2));
#pragma unroll
            for (int nf2 = 0; nf2 < 4; nf2++) {
                uint32_t off = swz((b_r0 + nf2 * 16) * 128 + (ks * 16 + b_kl) * 2);
                uint32_t bh[4];
                ldsm4(bh, sb + WO + off);
#pragma unroll
                for (int half = 0; half < 2; half++) {
                    int nf = nf2 * 2 + half;
                    uint32_t bhp[2] = {bh[half * 2], bh[half * 2 + 1]};
#pragma unroll
                    for (int mf = 0; mf < 2; mf++)
                        mma_f16(acc[mf][nf], ah[mf], bhp);
                }
            }
        }
        __syncthreads();
    }
    // epilogue: +bias, relu, fp16 store
    int er0 = rowBase + wm * 32 + (l >> 2);
    int ec0 = colBase + wn * 64 + (l & 3) * 2;
#pragma unroll
    for (int nf = 0; nf < 8; nf++) {
        int col = ec0 + nf * 8;
        float bx = __ldg(b1 + col), by = __ldg(b1 + col + 1);
#pragma unroll
        for (int mf = 0; mf < 2; mf++) {
#pragma unroll
            for (int half = 0; half < 2; half++) {
                int row = er0 + mf * 16 + half * 8;
                if (row < N_NODES) {
                    float v0 = fmaxf(acc[mf][nf][half * 2 + 0] + bx, 0.f);
                    float v1 = fmaxf(acc[mf][nf][half * 2 + 1] + by, 0.f);
                    *(uint32_t*)(g_H + (size_t)row * 256 + col) =
                        pack_h2(__float2half(v0), __float2half(v1));
                }
            }
        }
    }
}

// ---------------- GEMM2 (HMMA fp16): [yl|yr] = H @ W2^T, N=96 ----------------
__global__ __launch_bounds__(256) void gemm2_mma() {
    extern __shared__ __align__(1024) char smm[];
    const int AO = 0, WO = 16384;  // W tile: 96x64x2B = 12KB
    uint32_t sb = smem_u32(smm);
    int tid = threadIdx.x, l = tid & 31, wid = tid >> 5;
    int wm = wid & 3, wn = wid >> 2;
    int rowBase = blockIdx.x * 128;

    float acc[2][6][4];
#pragma unroll
    for (int i = 0; i < 2; i++)
#pragma unroll
        for (int j = 0; j < 6; j++)
#pragma unroll
            for (int q = 0; q < 4; q++) acc[i][j][q] = 0.f;

    int a_r0 = wm * 32 + (l & 7) + (l & 8);
    int a_kl = (l >> 4) * 8;
    int b_r0 = wn * 48 + (l & 7) + ((l >> 4) & 1) * 8;
    int b_kl = ((l >> 3) & 1) * 8;

    for (int c = 0; c < 4; c++) {
#pragma unroll
        for (int hh = 0; hh < 4; hh++) {
            int i = tid + hh * 256;
            int r = i >> 3, s = i & 7;
            uint32_t so = swz(r * 128 + s * 16);
            int row = rowBase + r;
            int4 va = make_int4(0, 0, 0, 0);
            if (row < N_NODES)
                va = *(const int4*)((const char*)g_H + (size_t)row * 512 + c * 128 + s * 16);
            *(int4*)(smm + AO + so) = va;
        }
#pragma unroll
        for (int hh = 0; hh < 3; hh++) {
            int i = tid + hh * 256;
            int r = i >> 3, s = i & 7;
            uint32_t so = swz(r * 128 + s * 16);
            *(int4*)(smm + WO + so) =
                *(const int4*)((const char*)g_W2t + (size_t)r * 512 + c * 128 + s * 16);
        }
        __syncthreads();
#pragma unroll
        for (int ks = 0; ks < 4; ks++) {
            uint32_t ah[2][4];
#pragma unroll
            for (int mf = 0; mf < 2; mf++)
                ldsm4(ah[mf], sb + AO + swz((a_r0 + mf * 16) * 128 + (ks * 16 + a_kl) * 2));
#pragma unroll
            for (int nf2 = 0; nf2 < 3; nf2++) {
                uint32_t off = swz((b_r0 + nf2 * 16) * 128 + (ks * 16 + b_kl) * 2);
                uint32_t bh[4];
                ldsm4(bh, sb + WO + off);
#pragma unroll
                for (int half = 0; half < 2; half++) {
                    int nf = nf2 * 2 + half;
                    uint32_t bhp[2] = {bh[half * 2], bh[half * 2 + 1]};
#pragma unroll
                    for (int mf = 0; mf < 2; mf++)
                        mma_f16(acc[mf][nf], ah[mf], bhp);
                }
            }
        }
        __syncthreads();
    }
    int er0 = rowBase + wm * 32 + (l >> 2);
    int ec0 = wn * 48 + (l & 3) * 2;
#pragma unroll
    for (int nf = 0; nf < 6; nf++) {
        int col = ec0 + nf * 8;
#pragma unroll
        for (int mf = 0; mf < 2; mf++) {
#pragma unroll
            for (int half = 0; half < 2; half++) {
                int row = er0 + mf * 16 + half * 8;
                if (row >= N_NODES) continue;
                float2 v = make_float2(acc[mf][nf][half * 2 + 0], acc[mf][nf][half * 2 + 1]);
                if (col < 48)
                    *(float2*)(g_yl + (size_t)row * OUTP + col) = v;
                else
                    *(float2*)(g_yr + (size_t)row * OUTP + col - 48) = v;
            }
        }
    }
}

// ---------------- final: mean-agg of yl + b2 + yr + log_softmax ----------------
__global__ void final_kernel(const float* __restrict__ b2, float* __restrict__ out) {
    int w = (blockIdx.x * blockDim.x + threadIdx.x) >> 5;
    if (w >= N_NODES) return;
    int lane = threadIdx.x & 31;
    int beg = g_off[w], end = g_off[w + 1];
    float inv = 1.f / (float)max(end - beg, 1);
    bool act = lane < 24;
    const float2* ylv = (const float2*)g_yl;
    float2 acc = make_float2(0.f, 0.f);
    for (int e = beg; e < end; e++) {
        int s = g_srcs[e];
        if (act) {
            float2 v = ylv[(size_t)s * 24 + lane];
            acc.x += v.x; acc.y += v.y;
        }
    }
    int c0 = lane * 2, c1 = lane * 2 + 1;
    float z0 = -1e30f, z1 = -1e30f;
    if (c0 < OUT_C) z0 = acc.x * inv + b2[c0] + g_yr[(size_t)w * OUTP + c0];
    if (c1 < OUT_C) z1 = acc.y * inv + b2[c1] + g_yr[(size_t)w * OUTP + c1];
    float m = fmaxf(z0, z1);
#pragma unroll
    for (int o = 16; o > 0; o >>= 1) m = fmaxf(m, __shfl_xor_sync(0xffffffffu, m, o));
    float s = 0.f;
    if (c0 < OUT_C) s += expf(z0 - m);
    if (c1 < OUT_C) s += expf(z1 - m);
#pragma unroll
    for (int o = 16; o > 0; o >>= 1) s += __shfl_xor_sync(0xffffffffu, s, o);
    float l = logf(s);
    if (c0 < OUT_C) out[(size_t)w * OUT_C + c0] = z0 - m - l;
    if (c1 < OUT_C) out[(size_t)w * OUT_C + c1] = z1 - m - l;
}

// ---------------- launch ----------------
extern "C" void kernel_launch(void* const* d_in, const int* in_sizes, int n_in,
                              void* d_out, int out_size) {
    const float* x   = (const float*)d_in[0];
    const void*  ei  = d_in[1];
    const float* W1l = (const float*)d_in[2];
    const float* b1  = (const float*)d_in[3];
    const float* W1r = (const float*)d_in[4];
    const float* W2l = (const float*)d_in[5];
    const float* b2  = (const float*)d_in[6];
    const float* W2r = (const float*)d_in[7];
    float* out = (float*)d_out;

    const int SMEM1 = 32768;
    const int SMEM2 = 28672;
    cudaFuncSetAttribute(gemm1_mma, cudaFuncAttributeMaxDynamicSharedMemorySize, SMEM1);
    cudaFuncSetAttribute(gemm2_mma, cudaFuncAttributeMaxDynamicSharedMemorySize, SMEM2);

    const int scan_blocks = (N_NODES + SCAN_B - 1) / SCAN_B;

    prep_kernel<<<(N_NODES * 32 + 255) / 256, 256>>>(x, (const int*)ei);
    hist_kernel<<<(N_EDGES + 255) / 256, 256>>>(ei);
    scanA_kernel<<<scan_blocks, SCAN_B>>>();
    scanC_kernel<<<scan_blocks, SCAN_B>>>();
    scatter_kernel<<<(N_EDGES + 255) / 256, 256>>>(ei);

    convw_kernel<<<(256 * 256 + 96 * 256 + 255) / 256, 256>>>(W1l, W1r, W2l, W2r);
    agg1_kernel<<<(N_NODES * 32 + 255) / 256, 256>>>();

    const int tiles = (N_NODES + 127) / 128;  // 782
    dim3 g1(tiles, 2);
    gemm1_mma<<<g1, 256, SMEM1>>>(b1);
    gemm2_mma<<<tiles, 256, SMEM2>>>();

    final_kernel<<<(N_NODES * 32 + 255) / 256, 256>>>(b2, out);
}

// round 6
// speedup vs baseline: 2.5086x; 1.1354x over previous
#include <cuda_runtime.h>
#include <cuda_fp16.h>
#include <math.h>
#include <stdint.h>

#define N_NODES 100000
#define N_EDGES 1600000
#define IN_C    128
#define HID_C   256
#define OUT_C   47
#define OUTP    48

// ---------------- scratch (static __device__, no allocs) ----------------
__device__ __align__(256) __half g_Xh[(size_t)N_NODES * IN_C];   // x fp16 (25.6MB)
__device__ __align__(256) __half g_M[(size_t)N_NODES * IN_C];    // mean(x_nbr) fp16 (25.6MB)
__device__ __align__(256) __half g_H[(size_t)N_NODES * HID_C];   // relu(h) fp16 (51.2MB)
__device__ __align__(256) __half g_W1t[256 * 256];  // [W1l;W1r]^T fp16 (n-major)
__device__ __align__(256) __half g_W2t[96 * 256];   // padded [W2l|W2r]^T fp16
__device__ __align__(256) __half g_ylh[(size_t)N_NODES * OUTP]; // h@W2l fp16 (9.6MB)
__device__ __align__(256) float  g_yr[(size_t)N_NODES * OUTP];  // h@W2r fp32
__device__ int   g_deg[N_NODES];
__device__ int   g_off[N_NODES + 1];
__device__ int   g_cur[N_NODES];
__device__ int   g_srcs[N_EDGES];
__device__ int   g_bsum[128];
__device__ int   g_is64;

// ---------------- helpers ----------------
__device__ __forceinline__ uint32_t smem_u32(const void* p) {
    uint32_t a;
    asm("{ .reg .u64 t; cvta.to.shared.u64 t, %1; cvt.u32.u64 %0, t; }" : "=r"(a) : "l"(p));
    return a;
}
__device__ __forceinline__ uint32_t swz(uint32_t o) { return o ^ ((o >> 3) & 0x70); }

__device__ __forceinline__ void ldsm4(uint32_t* r, uint32_t addr) {
    asm volatile("ldmatrix.sync.aligned.m8n8.x4.shared.b16 {%0,%1,%2,%3}, [%4];"
        : "=r"(r[0]), "=r"(r[1]), "=r"(r[2]), "=r"(r[3]) : "r"(addr));
}
__device__ __forceinline__ void mma_f16(float* c, const uint32_t* a, const uint32_t* b) {
    asm volatile("mma.sync.aligned.m16n8k16.row.col.f32.f16.f16.f32 "
        "{%0,%1,%2,%3}, {%4,%5,%6,%7}, {%8,%9}, {%0,%1,%2,%3};"
        : "+f"(c[0]), "+f"(c[1]), "+f"(c[2]), "+f"(c[3])
        : "r"(a[0]), "r"(a[1]), "r"(a[2]), "r"(a[3]), "r"(b[0]), "r"(b[1]));
}
__device__ __forceinline__ uint32_t pack_h2(__half a, __half b) {
    __half2 t; t.x = a; t.y = b;
    return *(uint32_t*)&t;
}
__device__ __forceinline__ void cp16(uint32_t sm, const void* g, bool v) {
    int sz = v ? 16 : 0;
    asm volatile("cp.async.cg.shared.global [%0], [%1], 16, %2;"
        :: "r"(sm), "l"(g), "r"(sz));
}
#define CP_COMMIT()  asm volatile("cp.async.commit_group;" ::: "memory")
#define CP_WAIT(n)   asm volatile("cp.async.wait_group %0;" :: "n"(n) : "memory")

// ---------------- edge dtype ----------------
__device__ __forceinline__ int edge_src(const void* p, int e) {
    return g_is64 ? (int)((const long long*)p)[e] : ((const int*)p)[e];
}
__device__ __forceinline__ int edge_dst(const void* p, int e) {
    return g_is64 ? (int)((const long long*)p)[N_EDGES + e] : ((const int*)p)[N_EDGES + e];
}

// ---------------- fused: deg-zero + dtype detect + x->fp16 ----------------
__global__ void prep_kernel(const float* __restrict__ x, const int* __restrict__ e32) {
    int t = blockIdx.x * blockDim.x + threadIdx.x;
    if (t < N_NODES) g_deg[t] = 0;
    if (t == 0) {
        int nz = 0;
        for (int q = 0; q < 64; q++) nz |= e32[2 * q + 1];
        g_is64 = (nz == 0) ? 1 : 0;
    }
    if (t >= N_NODES * 32) return;
    int row = t >> 5, q = t & 31;
    float4 v = ((const float4*)x)[(size_t)row * 32 + q];
    *(uint2*)(g_Xh + (size_t)row * 128 + q * 4) = make_uint2(
        pack_h2(__float2half(v.x), __float2half(v.y)),
        pack_h2(__float2half(v.z), __float2half(v.w)));
}

// ---------------- CSR build ----------------
__global__ void hist_kernel(const void* __restrict__ ei) {
    int e = blockIdx.x * blockDim.x + threadIdx.x;
    if (e < N_EDGES) atomicAdd(&g_deg[edge_dst(ei, e)], 1);
}
#define SCAN_B 1024
__global__ void scanA_kernel() {
    __shared__ int sm[SCAN_B];
    int tid = threadIdx.x;
    int i = blockIdx.x * SCAN_B + tid;
    int v = (i < N_NODES) ? g_deg[i] : 0;
    sm[tid] = v;
    __syncthreads();
    for (int off = 1; off < SCAN_B; off <<= 1) {
        int t = (tid >= off) ? sm[tid - off] : 0;
        __syncthreads();
        sm[tid] += t;
        __syncthreads();
    }
    if (i < N_NODES) g_off[i + 1] = sm[tid];
    if (tid == SCAN_B - 1) g_bsum[blockIdx.x] = sm[tid];
}
__global__ void scanC_kernel() {
    __shared__ int wsum[4];
    __shared__ int base_s;
    int tid = threadIdx.x;
    int b = blockIdx.x;
    if (tid < 128) {
        int v = (tid < b) ? g_bsum[tid] : 0;
#pragma unroll
        for (int o = 16; o > 0; o >>= 1) v += __shfl_xor_sync(0xffffffffu, v, o);
        if ((tid & 31) == 0) wsum[tid >> 5] = v;
    }
    __syncthreads();
    if (tid == 0) base_s = wsum[0] + wsum[1] + wsum[2] + wsum[3];
    __syncthreads();
    int base = base_s;
    int i = b * SCAN_B + tid;
    if (i < N_NODES) {
        int v = g_off[i + 1] + base;
        g_off[i + 1] = v;
        g_cur[i] = v - g_deg[i];
    }
    if (i == 0) g_off[0] = 0;
}
__global__ void scatter_kernel(const void* __restrict__ ei) {
    int e = blockIdx.x * blockDim.x + threadIdx.x;
    if (e < N_EDGES) {
        int s = edge_src(ei, e);
        int d = edge_dst(ei, e);
        int p = atomicAdd(&g_cur[d], 1);
        g_srcs[p] = s;
    }
}

// ---------------- weights: transpose to fp16 ----------------
__global__ void convw_kernel(const float* __restrict__ W1l, const float* __restrict__ W1r,
                             const float* __restrict__ W2l, const float* __restrict__ W2r) {
    int idx = blockIdx.x * blockDim.x + threadIdx.x;
    if (idx < 256 * 256) {
        int n = idx >> 8, k = idx & 255;
        float v = (k < 128) ? W1l[(size_t)k * 256 + n] : W1r[(size_t)(k - 128) * 256 + n];
        g_W1t[idx] = __float2half(v);
    } else if (idx < 256 * 256 + 96 * 256) {
        int j = idx - 256 * 256;
        int n = j >> 8, k = j & 255;
        float v = 0.f;
        if (n < 47) v = W2l[(size_t)k * 47 + n];
        else if (n >= 48 && n < 95) v = W2r[(size_t)k * 47 + (n - 48)];
        g_W2t[j] = __float2half(v);
    }
}

// ---------------- agg1: mean of fp16 x over in-neighbors -> g_M ----------------
__global__ void agg1_kernel() {
    int w = (blockIdx.x * blockDim.x + threadIdx.x) >> 5;
    if (w >= N_NODES) return;
    int lane = threadIdx.x & 31;
    int beg = g_off[w], end = g_off[w + 1];
    const uint2* xv = (const uint2*)g_Xh;
    float4 acc = make_float4(0.f, 0.f, 0.f, 0.f);
    for (int e0 = beg; e0 < end; e0 += 32) {
        int me = e0 + lane;
        int s = (me < end) ? g_srcs[me] : 0;
        int cnt = min(32, end - e0);
        for (int j = 0; j < cnt; j++) {
            int sj = __shfl_sync(0xffffffffu, s, j);
            uint2 p = xv[(size_t)sj * 32 + lane];
            float2 a = __half22float2(*(__half2*)&p.x);
            float2 b = __half22float2(*(__half2*)&p.y);
            acc.x += a.x; acc.y += a.y; acc.z += b.x; acc.w += b.y;
        }
    }
    float inv = 1.f / (float)max(end - beg, 1);
    *(uint2*)(g_M + (size_t)w * 128 + lane * 4) = make_uint2(
        pack_h2(__float2half(acc.x * inv), __float2half(acc.y * inv)),
        pack_h2(__float2half(acc.z * inv), __float2half(acc.w * inv)));
}

// ---------------- GEMM1 (HMMA fp16, cp.async double-buffer) ----------------
// h = relu([M|X] @ W1^T + b1); BM=128, BN=128 (grid.y=2), BK=64 x 4 chunks
__global__ __launch_bounds__(256) void gemm1_mma(const float* __restrict__ b1) {
    extern __shared__ __align__(1024) char smm[];
    const int BUF = 49152, AO = 0, WO = 16384;
    uint32_t sb = smem_u32(smm);
    int tid = threadIdx.x, l = tid & 31, wid = tid >> 5;
    int wm = wid & 3, wn = wid >> 2;
    int rowBase = blockIdx.x * 128, colBase = blockIdx.y * 128;

    float acc[2][8][4];
#pragma unroll
    for (int i = 0; i < 2; i++)
#pragma unroll
        for (int j = 0; j < 8; j++)
#pragma unroll
            for (int q = 0; q < 4; q++) acc[i][j][q] = 0.f;

    int a_r0 = wm * 32 + (l & 7) + (l & 8);
    int a_kl = (l >> 4) * 8;
    int b_r0 = wn * 64 + (l & 7) + ((l >> 4) & 1) * 8;
    int b_kl = ((l >> 3) & 1) * 8;

    auto load_chunk = [&](int c, int buf) {
#pragma unroll
        for (int hh = 0; hh < 4; hh++) {
            int i = tid + hh * 256;
            int r = i >> 3, s = i & 7;
            uint32_t so = swz(r * 128 + s * 16);
            int row = rowBase + r;
            bool ok = row < N_NODES;
            int rc = ok ? row : 0;
            const char* asrc = (c < 2)
                ? ((const char*)g_M + (size_t)rc * 256 + c * 128 + s * 16)
                : ((const char*)g_Xh + (size_t)rc * 256 + (c - 2) * 128 + s * 16);
            cp16(sb + buf * BUF + AO + so, asrc, ok);
            cp16(sb + buf * BUF + WO + so,
                 (const char*)g_W1t + (size_t)(colBase + r) * 512 + c * 128 + s * 16, true);
        }
        CP_COMMIT();
    };

    load_chunk(0, 0);
#pragma unroll
    for (int c = 0; c < 4; c++) {
        if (c < 3) { load_chunk(c + 1, (c + 1) & 1); CP_WAIT(1); }
        else CP_WAIT(0);
        __syncthreads();
        uint32_t bbase = sb + (c & 1) * BUF;
#pragma unroll
        for (int ks = 0; ks < 4; ks++) {
            uint32_t ah[2][4];
#pragma unroll
            for (int mf = 0; mf < 2; mf++)
                ldsm4(ah[mf], bbase + AO + swz((a_r0 + mf * 16) * 128 + (ks * 16 + a_kl) * 2));
#pragma unroll
            for (int nf2 = 0; nf2 < 4; nf2++) {
                uint32_t off = swz((b_r0 + nf2 * 16) * 128 + (ks * 16 + b_kl) * 2);
                uint32_t bh[4];
                ldsm4(bh, bbase + WO + off);
#pragma unroll
                for (int half = 0; half < 2; half++) {
                    int nf = nf2 * 2 + half;
                    uint32_t bhp[2] = {bh[half * 2], bh[half * 2 + 1]};
#pragma unroll
                    for (int mf = 0; mf < 2; mf++)
                        mma_f16(acc[mf][nf], ah[mf], bhp);
                }
            }
        }
        __syncthreads();
    }
    // epilogue: +bias, relu, fp16 store
    int er0 = rowBase + wm * 32 + (l >> 2);
    int ec0 = colBase + wn * 64 + (l & 3) * 2;
#pragma unroll
    for (int nf = 0; nf < 8; nf++) {
        int col = ec0 + nf * 8;
        float bx = __ldg(b1 + col), by = __ldg(b1 + col + 1);
#pragma unroll
        for (int mf = 0; mf < 2; mf++) {
#pragma unroll
            for (int half = 0; half < 2; half++) {
                int row = er0 + mf * 16 + half * 8;
                if (row < N_NODES) {
                    float v0 = fmaxf(acc[mf][nf][half * 2 + 0] + bx, 0.f);
                    float v1 = fmaxf(acc[mf][nf][half * 2 + 1] + by, 0.f);
                    *(uint32_t*)(g_H + (size_t)row * 256 + col) =
                        pack_h2(__float2half(v0), __float2half(v1));
                }
            }
        }
    }
}

// ---------------- GEMM2 (HMMA fp16, cp.async double-buffer): N=96 ----------------
__global__ __launch_bounds__(256) void gemm2_mma() {
    extern __shared__ __align__(1024) char smm[];
    const int BUF = 32768, AO = 0, WO = 16384;
    uint32_t sb = smem_u32(smm);
    int tid = threadIdx.x, l = tid & 31, wid = tid >> 5;
    int wm = wid & 3, wn = wid >> 2;
    int rowBase = blockIdx.x * 128;

    float acc[2][6][4];
#pragma unroll
    for (int i = 0; i < 2; i++)
#pragma unroll
        for (int j = 0; j < 6; j++)
#pragma unroll
            for (int q = 0; q < 4; q++) acc[i][j][q] = 0.f;

    int a_r0 = wm * 32 + (l & 7) + (l & 8);
    int a_kl = (l >> 4) * 8;
    int b_r0 = wn * 48 + (l & 7) + ((l >> 4) & 1) * 8;
    int b_kl = ((l >> 3) & 1) * 8;

    auto load_chunk = [&](int c, int buf) {
#pragma unroll
        for (int hh = 0; hh < 4; hh++) {
            int i = tid + hh * 256;
            int r = i >> 3, s = i & 7;
            uint32_t so = swz(r * 128 + s * 16);
            int row = rowBase + r;
            bool ok = row < N_NODES;
            int rc = ok ? row : 0;
            cp16(sb + buf * BUF + AO + so,
                 (const char*)g_H + (size_t)rc * 512 + c * 128 + s * 16, ok);
        }
#pragma unroll
        for (int hh = 0; hh < 3; hh++) {
            int i = tid + hh * 256;
            int r = i >> 3, s = i & 7;
            uint32_t so = swz(r * 128 + s * 16);
            cp16(sb + buf * BUF + WO + so,
                 (const char*)g_W2t + (size_t)r * 512 + c * 128 + s * 16, true);
        }
        CP_COMMIT();
    };

    load_chunk(0, 0);
#pragma unroll
    for (int c = 0; c < 4; c++) {
        if (c < 3) { load_chunk(c + 1, (c + 1) & 1); CP_WAIT(1); }
        else CP_WAIT(0);
        __syncthreads();
        uint32_t bbase = sb + (c & 1) * BUF;
#pragma unroll
        for (int ks = 0; ks < 4; ks++) {
            uint32_t ah[2][4];
#pragma unroll
            for (int mf = 0; mf < 2; mf++)
                ldsm4(ah[mf], bbase + AO + swz((a_r0 + mf * 16) * 128 + (ks * 16 + a_kl) * 2));
#pragma unroll
            for (int nf2 = 0; nf2 < 3; nf2++) {
                uint32_t off = swz((b_r0 + nf2 * 16) * 128 + (ks * 16 + b_kl) * 2);
                uint32_t bh[4];
                ldsm4(bh, bbase + WO + off);
#pragma unroll
                for (int half = 0; half < 2; half++) {
                    int nf = nf2 * 2 + half;
                    uint32_t bhp[2] = {bh[half * 2], bh[half * 2 + 1]};
#pragma unroll
                    for (int mf = 0; mf < 2; mf++)
                        mma_f16(acc[mf][nf], ah[mf], bhp);
                }
            }
        }
        __syncthreads();
    }
    int er0 = rowBase + wm * 32 + (l >> 2);
    int ec0 = wn * 48 + (l & 3) * 2;
#pragma unroll
    for (int nf = 0; nf < 6; nf++) {
        int col = ec0 + nf * 8;
#pragma unroll
        for (int mf = 0; mf < 2; mf++) {
#pragma unroll
            for (int half = 0; half < 2; half++) {
                int row = er0 + mf * 16 + half * 8;
                if (row >= N_NODES) continue;
                float v0 = acc[mf][nf][half * 2 + 0];
                float v1 = acc[mf][nf][half * 2 + 1];
                if (col < 48)
                    *(uint32_t*)(g_ylh + (size_t)row * OUTP + col) =
                        pack_h2(__float2half(v0), __float2half(v1));
                else
                    *(float2*)(g_yr + (size_t)row * OUTP + col - 48) = make_float2(v0, v1);
            }
        }
    }
}

// ---------------- final: mean-agg of ylh (fp16) + b2 + yr + log_softmax ----------------
__global__ void final_kernel(const float* __restrict__ b2, float* __restrict__ out) {
    int w = (blockIdx.x * blockDim.x + threadIdx.x) >> 5;
    if (w >= N_NODES) return;
    int lane = threadIdx.x & 31;
    int beg = g_off[w], end = g_off[w + 1];
    float inv = 1.f / (float)max(end - beg, 1);
    bool act = lane < 24;
    const uint32_t* ylv = (const uint32_t*)g_ylh;
    float2 acc = make_float2(0.f, 0.f);
    for (int e0 = beg; e0 < end; e0 += 32) {
        int me = e0 + lane;
        int s = (me < end) ? g_srcs[me] : 0;
        int cnt = min(32, end - e0);
        for (int j = 0; j < cnt; j++) {
            int sj = __shfl_sync(0xffffffffu, s, j);
            if (act) {
                uint32_t p = ylv[(size_t)sj * 24 + lane];
                float2 v = __half22float2(*(__half2*)&p);
                acc.x += v.x; acc.y += v.y;
            }
        }
    }
    int c0 = lane * 2, c1 = lane * 2 + 1;
    float z0 = -1e30f, z1 = -1e30f;
    if (c0 < OUT_C) z0 = acc.x * inv + b2[c0] + g_yr[(size_t)w * OUTP + c0];
    if (c1 < OUT_C) z1 = acc.y * inv + b2[c1] + g_yr[(size_t)w * OUTP + c1];
    float m = fmaxf(z0, z1);
#pragma unroll
    for (int o = 16; o > 0; o >>= 1) m = fmaxf(m, __shfl_xor_sync(0xffffffffu, m, o));
    float s = 0.f;
    if (c0 < OUT_C) s += expf(z0 - m);
    if (c1 < OUT_C) s += expf(z1 - m);
#pragma unroll
    for (int o = 16; o > 0; o >>= 1) s += __shfl_xor_sync(0xffffffffu, s, o);
    float l = logf(s);
    if (c0 < OUT_C) out[(size_t)w * OUT_C + c0] = z0 - m - l;
    if (c1 < OUT_C) out[(size_t)w * OUT_C + c1] = z1 - m - l;
}

// ---------------- launch ----------------
extern "C" void kernel_launch(void* const* d_in, const int* in_sizes, int n_in,
                              void* d_out, int out_size) {
    const float* x   = (const float*)d_in[0];
    const void*  ei  = d_in[1];
    const float* W1l = (const float*)d_in[2];
    const float* b1  = (const float*)d_in[3];
    const float* W1r = (const float*)d_in[4];
    const float* W2l = (const float*)d_in[5];
    const float* b2  = (const float*)d_in[6];
    const float* W2r = (const float*)d_in[7];
    float* out = (float*)d_out;

    const int SMEM1 = 98304;   // 2 x (16KB A + 32KB W)
    const int SMEM2 = 65536;   // 2 x (16KB A + 12KB W, padded to 32KB)
    cudaFuncSetAttribute(gemm1_mma, cudaFuncAttributeMaxDynamicSharedMemorySize, SMEM1);
    cudaFuncSetAttribute(gemm2_mma, cudaFuncAttributeMaxDynamicSharedMemorySize, SMEM2);

    const int scan_blocks = (N_NODES + SCAN_B - 1) / SCAN_B;

    prep_kernel<<<(N_NODES * 32 + 255) / 256, 256>>>(x, (const int*)ei);
    hist_kernel<<<(N_EDGES + 255) / 256, 256>>>(ei);
    scanA_kernel<<<scan_blocks, SCAN_B>>>();
    scanC_kernel<<<scan_blocks, SCAN_B>>>();
    scatter_kernel<<<(N_EDGES + 255) / 256, 256>>>(ei);

    convw_kernel<<<(256 * 256 + 96 * 256 + 255) / 256, 256>>>(W1l, W1r, W2l, W2r);
    agg1_kernel<<<(N_NODES * 32 + 255) / 256, 256>>>();

    const int tiles = (N_NODES + 127) / 128;  // 782
    dim3 g1(tiles, 2);
    gemm1_mma<<<g1, 256, SMEM1>>>(b1);
    gemm2_mma<<<tiles, 256, SMEM2>>>();

    final_kernel<<<(N_NODES * 32 + 255) / 256, 256>>>(b2, out);
}

// round 7
// speedup vs baseline: 2.5955x; 1.0346x over previous
#include <cuda_runtime.h>
#include <cuda_fp16.h>
#include <math.h>
#include <stdint.h>

#define N_NODES 100000
#define N_EDGES 1600000
#define IN_C    128
#define HID_C   256
#define OUT_C   47
#define OUTP    48

// ---------------- scratch (static __device__, no allocs) ----------------
__device__ __align__(256) __half g_Xh[(size_t)N_NODES * IN_C];   // x fp16 (25.6MB)
__device__ __align__(256) __half g_M[(size_t)N_NODES * IN_C];    // mean(x_nbr) fp16
__device__ __align__(256) __half g_H[(size_t)N_NODES * HID_C];   // relu(h) fp16
__device__ __align__(256) __half g_W1t[256 * 256];  // [W1l;W1r]^T fp16 (n-major)
__device__ __align__(256) __half g_W2t[96 * 256];   // padded [W2l|W2r]^T fp16
__device__ __align__(256) __half g_ylh[(size_t)N_NODES * OUTP]; // h@W2l fp16
__device__ __align__(256) float  g_yr[(size_t)N_NODES * OUTP];  // h@W2r fp32
__device__ int   g_deg[N_NODES];
__device__ int   g_off[N_NODES + 1];
__device__ int   g_cur[N_NODES];
__device__ int   g_srcs[N_EDGES];
__device__ int   g_bsum[128];
__device__ int   g_is64;

// ---------------- helpers ----------------
__device__ __forceinline__ uint32_t smem_u32(const void* p) {
    uint32_t a;
    asm("{ .reg .u64 t; cvta.to.shared.u64 t, %1; cvt.u32.u64 %0, t; }" : "=r"(a) : "l"(p));
    return a;
}
__device__ __forceinline__ uint32_t swz(uint32_t o) { return o ^ ((o >> 3) & 0x70); }

__device__ __forceinline__ void ldsm4(uint32_t* r, uint32_t addr) {
    asm volatile("ldmatrix.sync.aligned.m8n8.x4.shared.b16 {%0,%1,%2,%3}, [%4];"
        : "=r"(r[0]), "=r"(r[1]), "=r"(r[2]), "=r"(r[3]) : "r"(addr));
}
__device__ __forceinline__ void mma_f16(float* c, const uint32_t* a, const uint32_t* b) {
    asm volatile("mma.sync.aligned.m16n8k16.row.col.f32.f16.f16.f32 "
        "{%0,%1,%2,%3}, {%4,%5,%6,%7}, {%8,%9}, {%0,%1,%2,%3};"
        : "+f"(c[0]), "+f"(c[1]), "+f"(c[2]), "+f"(c[3])
        : "r"(a[0]), "r"(a[1]), "r"(a[2]), "r"(a[3]), "r"(b[0]), "r"(b[1]));
}
__device__ __forceinline__ uint32_t pack_h2(__half a, __half b) {
    __half2 t; t.x = a; t.y = b;
    return *(uint32_t*)&t;
}
__device__ __forceinline__ void cp16(uint32_t sm, const void* g, bool v) {
    int sz = v ? 16 : 0;
    asm volatile("cp.async.cg.shared.global [%0], [%1], 16, %2;"
        :: "r"(sm), "l"(g), "r"(sz));
}
#define CP_COMMIT()  asm volatile("cp.async.commit_group;" ::: "memory")
#define CP_WAIT(n)   asm volatile("cp.async.wait_group %0;" :: "n"(n) : "memory")

// ---------------- edge dtype ----------------
__device__ __forceinline__ int edge_src(const void* p, int e) {
    return g_is64 ? (int)((const long long*)p)[e] : ((const int*)p)[e];
}
__device__ __forceinline__ int edge_dst(const void* p, int e) {
    return g_is64 ? (int)((const long long*)p)[N_EDGES + e] : ((const int*)p)[N_EDGES + e];
}

// ---------------- stream-B head: deg zero + dtype detect ----------------
__global__ void zero_detect_kernel(const int* __restrict__ e32) {
    int i = blockIdx.x * blockDim.x + threadIdx.x;
    if (i < N_NODES) g_deg[i] = 0;
    if (i == 0) {
        int nz = 0;
        for (int q = 0; q < 64; q++) nz |= e32[2 * q + 1];
        g_is64 = (nz == 0) ? 1 : 0;
    }
}

// ---------------- x -> fp16 ----------------
__global__ void prep_kernel(const float* __restrict__ x) {
    int t = blockIdx.x * blockDim.x + threadIdx.x;
    if (t >= N_NODES * 32) return;
    int row = t >> 5, q = t & 31;
    float4 v = ((const float4*)x)[(size_t)row * 32 + q];
    *(uint2*)(g_Xh + (size_t)row * 128 + q * 4) = make_uint2(
        pack_h2(__float2half(v.x), __float2half(v.y)),
        pack_h2(__float2half(v.z), __float2half(v.w)));
}

// ---------------- CSR build ----------------
__global__ void hist_kernel(const void* __restrict__ ei) {
    int e = blockIdx.x * blockDim.x + threadIdx.x;
    if (e < N_EDGES) atomicAdd(&g_deg[edge_dst(ei, e)], 1);
}
#define SCAN_B 1024
__global__ void scanA_kernel() {
    __shared__ int sm[SCAN_B];
    int tid = threadIdx.x;
    int i = blockIdx.x * SCAN_B + tid;
    int v = (i < N_NODES) ? g_deg[i] : 0;
    sm[tid] = v;
    __syncthreads();
    for (int off = 1; off < SCAN_B; off <<= 1) {
        int t = (tid >= off) ? sm[tid - off] : 0;
        __syncthreads();
        sm[tid] += t;
        __syncthreads();
    }
    if (i < N_NODES) g_off[i + 1] = sm[tid];
    if (tid == SCAN_B - 1) g_bsum[blockIdx.x] = sm[tid];
}
__global__ void scanC_kernel() {
    __shared__ int wsum[4];
    __shared__ int base_s;
    int tid = threadIdx.x;
    int b = blockIdx.x;
    if (tid < 128) {
        int v = (tid < b) ? g_bsum[tid] : 0;
#pragma unroll
        for (int o = 16; o > 0; o >>= 1) v += __shfl_xor_sync(0xffffffffu, v, o);
        if ((tid & 31) == 0) wsum[tid >> 5] = v;
    }
    __syncthreads();
    if (tid == 0) base_s = wsum[0] + wsum[1] + wsum[2] + wsum[3];
    __syncthreads();
    int base = base_s;
    int i = b * SCAN_B + tid;
    if (i < N_NODES) {
        int v = g_off[i + 1] + base;
        g_off[i + 1] = v;
        g_cur[i] = v - g_deg[i];
    }
    if (i == 0) g_off[0] = 0;
}
__global__ void scatter_kernel(const void* __restrict__ ei) {
    int e = blockIdx.x * blockDim.x + threadIdx.x;
    if (e < N_EDGES) {
        int s = edge_src(ei, e);
        int d = edge_dst(ei, e);
        int p = atomicAdd(&g_cur[d], 1);
        g_srcs[p] = s;
    }
}

// ---------------- weights: transpose to fp16 ----------------
__global__ void convw_kernel(const float* __restrict__ W1l, const float* __restrict__ W1r,
                             const float* __restrict__ W2l, const float* __restrict__ W2r) {
    int idx = blockIdx.x * blockDim.x + threadIdx.x;
    if (idx < 256 * 256) {
        int n = idx >> 8, k = idx & 255;
        float v = (k < 128) ? W1l[(size_t)k * 256 + n] : W1r[(size_t)(k - 128) * 256 + n];
        g_W1t[idx] = __float2half(v);
    } else if (idx < 256 * 256 + 96 * 256) {
        int j = idx - 256 * 256;
        int n = j >> 8, k = j & 255;
        float v = 0.f;
        if (n < 47) v = W2l[(size_t)k * 47 + n];
        else if (n >= 48 && n < 95) v = W2r[(size_t)k * 47 + (n - 48)];
        g_W2t[j] = __float2half(v);
    }
}

// ---------------- agg1: mean of fp16 x over in-neighbors -> g_M ----------------
__global__ void agg1_kernel() {
    int w = (blockIdx.x * blockDim.x + threadIdx.x) >> 5;
    if (w >= N_NODES) return;
    int lane = threadIdx.x & 31;
    int beg = g_off[w], end = g_off[w + 1];
    const uint2* xv = (const uint2*)g_Xh;
    float4 acc = make_float4(0.f, 0.f, 0.f, 0.f);
    for (int e0 = beg; e0 < end; e0 += 32) {
        int me = e0 + lane;
        int s = (me < end) ? g_srcs[me] : 0;
        int cnt = min(32, end - e0);
        for (int j = 0; j < cnt; j++) {
            int sj = __shfl_sync(0xffffffffu, s, j);
            uint2 p = xv[(size_t)sj * 32 + lane];
            float2 a = __half22float2(*(__half2*)&p.x);
            float2 b = __half22float2(*(__half2*)&p.y);
            acc.x += a.x; acc.y += a.y; acc.z += b.x; acc.w += b.y;
        }
    }
    float inv = 1.f / (float)max(end - beg, 1);
    *(uint2*)(g_M + (size_t)w * 128 + lane * 4) = make_uint2(
        pack_h2(__float2half(acc.x * inv), __float2half(acc.y * inv)),
        pack_h2(__float2half(acc.z * inv), __float2half(acc.w * inv)));
}

// ---------------- GEMM1 (HMMA fp16, cp.async, BN=256 single pass) ----------------
// h = relu([M|X] @ W1^T + b1); BM=128, BN=256, BK=64 x 4 chunks; warp tile 32x128
__global__ __launch_bounds__(256) void gemm1_mma(const float* __restrict__ b1) {
    extern __shared__ __align__(1024) char smm[];
    const int BUF = 49152, AO = 0, WO = 16384;
    uint32_t sb = smem_u32(smm);
    int tid = threadIdx.x, l = tid & 31, wid = tid >> 5;
    int wm = wid & 3, wn = wid >> 2;
    int rowBase = blockIdx.x * 128;

    float acc[2][16][4];
#pragma unroll
    for (int i = 0; i < 2; i++)
#pragma unroll
        for (int j = 0; j < 16; j++)
#pragma unroll
            for (int q = 0; q < 4; q++) acc[i][j][q] = 0.f;

    int a_r0 = wm * 32 + (l & 7) + (l & 8);
    int a_kl = (l >> 4) * 8;
    int b_r0 = wn * 128 + (l & 7) + ((l >> 4) & 1) * 8;
    int b_kl = ((l >> 3) & 1) * 8;

    auto load_chunk = [&](int c, int buf) {
#pragma unroll
        for (int hh = 0; hh < 4; hh++) {
            int i = tid + hh * 256;
            int r = i >> 3, s = i & 7;
            uint32_t so = swz(r * 128 + s * 16);
            int row = rowBase + r;
            bool ok = row < N_NODES;
            int rc = ok ? row : 0;
            const char* asrc = (c < 2)
                ? ((const char*)g_M + (size_t)rc * 256 + c * 128 + s * 16)
                : ((const char*)g_Xh + (size_t)rc * 256 + (c - 2) * 128 + s * 16);
            cp16(sb + buf * BUF + AO + so, asrc, ok);
        }
#pragma unroll
        for (int hh = 0; hh < 8; hh++) {
            int i = tid + hh * 256;
            int r = i >> 3, s = i & 7;
            uint32_t so = swz(r * 128 + s * 16);
            cp16(sb + buf * BUF + WO + so,
                 (const char*)g_W1t + (size_t)r * 512 + c * 128 + s * 16, true);
        }
        CP_COMMIT();
    };

    load_chunk(0, 0);
#pragma unroll
    for (int c = 0; c < 4; c++) {
        if (c < 3) { load_chunk(c + 1, (c + 1) & 1); CP_WAIT(1); }
        else CP_WAIT(0);
        __syncthreads();
        uint32_t bbase = sb + (c & 1) * BUF;
#pragma unroll
        for (int ks = 0; ks < 4; ks++) {
            uint32_t ah[2][4];
#pragma unroll
            for (int mf = 0; mf < 2; mf++)
                ldsm4(ah[mf], bbase + AO + swz((a_r0 + mf * 16) * 128 + (ks * 16 + a_kl) * 2));
#pragma unroll
            for (int nf2 = 0; nf2 < 8; nf2++) {
                uint32_t off = swz((b_r0 + nf2 * 16) * 128 + (ks * 16 + b_kl) * 2);
                uint32_t bh[4];
                ldsm4(bh, bbase + WO + off);
#pragma unroll
                for (int half = 0; half < 2; half++) {
                    int nf = nf2 * 2 + half;
                    uint32_t bhp[2] = {bh[half * 2], bh[half * 2 + 1]};
#pragma unroll
                    for (int mf = 0; mf < 2; mf++)
                        mma_f16(acc[mf][nf], ah[mf], bhp);
                }
            }
        }
        __syncthreads();
    }
    // epilogue: +bias, relu, fp16 store
    int er0 = rowBase + wm * 32 + (l >> 2);
    int ec0 = wn * 128 + (l & 3) * 2;
#pragma unroll
    for (int nf = 0; nf < 16; nf++) {
        int col = ec0 + nf * 8;
        float bx = __ldg(b1 + col), by = __ldg(b1 + col + 1);
#pragma unroll
        for (int mf = 0; mf < 2; mf++) {
#pragma unroll
            for (int half = 0; half < 2; half++) {
                int row = er0 + mf * 16 + half * 8;
                if (row < N_NODES) {
                    float v0 = fmaxf(acc[mf][nf][half * 2 + 0] + bx, 0.f);
                    float v1 = fmaxf(acc[mf][nf][half * 2 + 1] + by, 0.f);
                    *(uint32_t*)(g_H + (size_t)row * 256 + col) =
                        pack_h2(__float2half(v0), __float2half(v1));
                }
            }
        }
    }
}

// ---------------- GEMM2 (HMMA fp16, cp.async double-buffer): N=96 ----------------
__global__ __launch_bounds__(256) void gemm2_mma() {
    extern __shared__ __align__(1024) char smm[];
    const int BUF = 32768, AO = 0, WO = 16384;
    uint32_t sb = smem_u32(smm);
    int tid = threadIdx.x, l = tid & 31, wid = tid >> 5;
    int wm = wid & 3, wn = wid >> 2;
    int rowBase = blockIdx.x * 128;

    float acc[2][6][4];
#pragma unroll
    for (int i = 0; i < 2; i++)
#pragma unroll
        for (int j = 0; j < 6; j++)
#pragma unroll
            for (int q = 0; q < 4; q++) acc[i][j][q] = 0.f;

    int a_r0 = wm * 32 + (l & 7) + (l & 8);
    int a_kl = (l >> 4) * 8;
    int b_r0 = wn * 48 + (l & 7) + ((l >> 4) & 1) * 8;
    int b_kl = ((l >> 3) & 1) * 8;

    auto load_chunk = [&](int c, int buf) {
#pragma unroll
        for (int hh = 0; hh < 4; hh++) {
            int i = tid + hh * 256;
            int r = i >> 3, s = i & 7;
            uint32_t so = swz(r * 128 + s * 16);
            int row = rowBase + r;
            bool ok = row < N_NODES;
            int rc = ok ? row : 0;
            cp16(sb + buf * BUF + AO + so,
                 (const char*)g_H + (size_t)rc * 512 + c * 128 + s * 16, ok);
        }
#pragma unroll
        for (int hh = 0; hh < 3; hh++) {
            int i = tid + hh * 256;
            int r = i >> 3, s = i & 7;
            uint32_t so = swz(r * 128 + s * 16);
            cp16(sb + buf * BUF + WO + so,
                 (const char*)g_W2t + (size_t)r * 512 + c * 128 + s * 16, true);
        }
        CP_COMMIT();
    };

    load_chunk(0, 0);
#pragma unroll
    for (int c = 0; c < 4; c++) {
        if (c < 3) { load_chunk(c + 1, (c + 1) & 1); CP_WAIT(1); }
        else CP_WAIT(0);
        __syncthreads();
        uint32_t bbase = sb + (c & 1) * BUF;
#pragma unroll
        for (int ks = 0; ks < 4; ks++) {
            uint32_t ah[2][4];
#pragma unroll
            for (int mf = 0; mf < 2; mf++)
                ldsm4(ah[mf], bbase + AO + swz((a_r0 + mf * 16) * 128 + (ks * 16 + a_kl) * 2));
#pragma unroll
            for (int nf2 = 0; nf2 < 3; nf2++) {
                uint32_t off = swz((b_r0 + nf2 * 16) * 128 + (ks * 16 + b_kl) * 2);
                uint32_t bh[4];
                ldsm4(bh, bbase + WO + off);
#pragma unroll
                for (int half = 0; half < 2; half++) {
                    int nf = nf2 * 2 + half;
                    uint32_t bhp[2] = {bh[half * 2], bh[half * 2 + 1]};
#pragma unroll
                    for (int mf = 0; mf < 2; mf++)
                        mma_f16(acc[mf][nf], ah[mf], bhp);
                }
            }
        }
        __syncthreads();
    }
    int er0 = rowBase + wm * 32 + (l >> 2);
    int ec0 = wn * 48 + (l & 3) * 2;
#pragma unroll
    for (int nf = 0; nf < 6; nf++) {
        int col = ec0 + nf * 8;
#pragma unroll
        for (int mf = 0; mf < 2; mf++) {
#pragma unroll
            for (int half = 0; half < 2; half++) {
                int row = er0 + mf * 16 + half * 8;
                if (row >= N_NODES) continue;
                float v0 = acc[mf][nf][half * 2 + 0];
                float v1 = acc[mf][nf][half * 2 + 1];
                if (col < 48)
                    *(uint32_t*)(g_ylh + (size_t)row * OUTP + col) =
                        pack_h2(__float2half(v0), __float2half(v1));
                else
                    *(float2*)(g_yr + (size_t)row * OUTP + col - 48) = make_float2(v0, v1);
            }
        }
    }
}

// ---------------- final: mean-agg of ylh (fp16) + b2 + yr + log_softmax ----------------
__global__ void final_kernel(const float* __restrict__ b2, float* __restrict__ out) {
    int w = (blockIdx.x * blockDim.x + threadIdx.x) >> 5;
    if (w >= N_NODES) return;
    int lane = threadIdx.x & 31;
    int beg = g_off[w], end = g_off[w + 1];
    float inv = 1.f / (float)max(end - beg, 1);
    bool act = lane < 24;
    const uint32_t* ylv = (const uint32_t*)g_ylh;
    float2 acc = make_float2(0.f, 0.f);
    for (int e0 = beg; e0 < end; e0 += 32) {
        int me = e0 + lane;
        int s = (me < end) ? g_srcs[me] : 0;
        int cnt = min(32, end - e0);
        for (int j = 0; j < cnt; j++) {
            int sj = __shfl_sync(0xffffffffu, s, j);
            if (act) {
                uint32_t p = ylv[(size_t)sj * 24 + lane];
                float2 v = __half22float2(*(__half2*)&p);
                acc.x += v.x; acc.y += v.y;
            }
        }
    }
    int c0 = lane * 2, c1 = lane * 2 + 1;
    float z0 = -1e30f, z1 = -1e30f;
    if (c0 < OUT_C) z0 = acc.x * inv + b2[c0] + g_yr[(size_t)w * OUTP + c0];
    if (c1 < OUT_C) z1 = acc.y * inv + b2[c1] + g_yr[(size_t)w * OUTP + c1];
    float m = fmaxf(z0, z1);
#pragma unroll
    for (int o = 16; o > 0; o >>= 1) m = fmaxf(m, __shfl_xor_sync(0xffffffffu, m, o));
    float s = 0.f;
    if (c0 < OUT_C) s += expf(z0 - m);
    if (c1 < OUT_C) s += expf(z1 - m);
#pragma unroll
    for (int o = 16; o > 0; o >>= 1) s += __shfl_xor_sync(0xffffffffu, s, o);
    float l = logf(s);
    if (c0 < OUT_C) out[(size_t)w * OUT_C + c0] = z0 - m - l;
    if (c1 < OUT_C) out[(size_t)w * OUT_C + c1] = z1 - m - l;
}

// ---------------- launch ----------------
extern "C" void kernel_launch(void* const* d_in, const int* in_sizes, int n_in,
                              void* d_out, int out_size) {
    const float* x   = (const float*)d_in[0];
    const void*  ei  = d_in[1];
    const float* W1l = (const float*)d_in[2];
    const float* b1  = (const float*)d_in[3];
    const float* W1r = (const float*)d_in[4];
    const float* W2l = (const float*)d_in[5];
    const float* b2  = (const float*)d_in[6];
    const float* W2r = (const float*)d_in[7];
    float* out = (float*)d_out;

    static cudaStream_t s2 = nullptr;
    static cudaEvent_t evF = nullptr, evJ = nullptr;
    if (!s2) {
        cudaStreamCreate(&s2);
        cudaEventCreateWithFlags(&evF, cudaEventDisableTiming);
        cudaEventCreateWithFlags(&evJ, cudaEventDisableTiming);
    }

    const int SMEM1 = 98304;   // 2 x (16KB A + 32KB W)
    const int SMEM2 = 65536;
    static bool attr_set = false;
    if (!attr_set) {
        cudaFuncSetAttribute(gemm1_mma, cudaFuncAttributeMaxDynamicSharedMemorySize, SMEM1);
        cudaFuncSetAttribute(gemm2_mma, cudaFuncAttributeMaxDynamicSharedMemorySize, SMEM2);
        attr_set = true;
    }

    const int scan_blocks = (N_NODES + SCAN_B - 1) / SCAN_B;

    // fork: s2 builds CSR while stream 0 converts x and weights
    cudaEventRecord(evF, 0);
    cudaStreamWaitEvent(s2, evF, 0);

    zero_detect_kernel<<<(N_NODES + 255) / 256, 256, 0, s2>>>((const int*)ei);
    hist_kernel<<<(N_EDGES + 255) / 256, 256, 0, s2>>>(ei);
    scanA_kernel<<<scan_blocks, SCAN_B, 0, s2>>>();
    scanC_kernel<<<scan_blocks, SCAN_B, 0, s2>>>();
    scatter_kernel<<<(N_EDGES + 255) / 256, 256, 0, s2>>>(ei);

    prep_kernel<<<(N_NODES * 32 + 255) / 256, 256>>>(x);
    convw_kernel<<<(256 * 256 + 96 * 256 + 255) / 256, 256>>>(W1l, W1r, W2l, W2r);

    // join
    cudaEventRecord(evJ, s2);
    cudaStreamWaitEvent(0, evJ, 0);

    agg1_kernel<<<(N_NODES * 32 + 255) / 256, 256>>>();

    const int tiles = (N_NODES + 127) / 128;  // 782
    gemm1_mma<<<tiles, 256, SMEM1>>>(b1);
    gemm2_mma<<<tiles, 256, SMEM2>>>();

    final_kernel<<<(N_NODES * 32 + 255) / 256, 256>>>(b2, out);
}